// round 1
// baseline (speedup 1.0000x reference)
#include <cuda_runtime.h>
#include <cuda_bf16.h>
#include <cstdint>
#include <cstdio>

// Problem constants
#define BB 2
#define LL 2048
#define KK 2048
#define DD 512
#define HH 8
#define HD 64
#define RR 8
#define WWIN 8
#define EE (LL*WWIN)          // 16384 edges per batch
#define EH 16
#define TT 2

// ---------------- scratch (allocation-free: static device globals) ----------------
__device__ float g_u [BB*HH*LL*HD];          // [B,H,L,HD]
__device__ float g_v [BB*HH*KK*HD];          // [B,H,K,HD]
__device__ float g_ut[BB*LL*DD];             // [B,L,D]
__device__ float g_SA[BB*LL*EH];             // target @ Ws1[:D]
__device__ float g_SB[BB*KK*EH];             // context @ Ws1[D:]
__device__ float g_AA[BB*LL*EH];
__device__ float g_AB[BB*KK*EH];
__device__ float g_LA[BB*LL*EH];
__device__ float g_LB[BB*KK*EH];
__device__ int   g_idx[BB*LL*WWIN];
__device__ float g_gh[BB*EE*EH];             // gelu(h) per edge for Lam GEMM
__device__ float g_alpha[BB*EE];
__device__ float g_cosv[BB*EE*32];
__device__ float g_sinv[BB*EE*32];
__device__ float g_Lam[(size_t)BB*EE*HH*RR*HD];  // 134,217,728 floats (512MB)

// ---------------- helpers ----------------
__device__ __forceinline__ float geluf(float x){
    return 0.5f * x * (1.0f + erff(x * 0.7071067811865475244f));
}
__device__ __forceinline__ float softplusf(float x){
    return (x > 20.f) ? x : log1pf(expf(x));
}

// ---------------- generic fp32 GEMM: C = A[MxK] @ W[KxN] + bias ----------------
// mode 0: C[m*N+n]
// mode 1: m=b*2048+l, n=h*64+hd -> C[((b*8+h)*2048+l)*64+hd]   (u/v layout)
// mode 2: normalize each 64-col chunk per row (for Lam), plain store
__global__ __launch_bounds__(256) void gemm_kernel(
    const float* __restrict__ A, const float* __restrict__ W,
    const float* __restrict__ bias, float* __restrict__ C,
    int M, int N, int Kd, int mode)
{
    __shared__ float As[16][68];
    __shared__ float Bs[16][64];
    const int bn = blockIdx.x * 64;
    const int bm = blockIdx.y * 64;
    const int tid = threadIdx.x;
    const int tx = tid & 15, ty = tid >> 4;

    float acc[4][4];
#pragma unroll
    for (int i = 0; i < 4; i++)
#pragma unroll
        for (int j = 0; j < 4; j++) acc[i][j] = 0.f;

    const int am = tid >> 2;
    const int akq = (tid & 3) * 4;
    const int bk = tid >> 4;
    const int bnq = (tid & 15) * 4;

    for (int k0 = 0; k0 < Kd; k0 += 16) {
        float4 av = *(const float4*)&A[(size_t)(bm + am) * Kd + k0 + akq];
        As[akq + 0][am] = av.x;
        As[akq + 1][am] = av.y;
        As[akq + 2][am] = av.z;
        As[akq + 3][am] = av.w;
        *(float4*)&Bs[bk][bnq] = *(const float4*)&W[(size_t)(k0 + bk) * N + bn + bnq];
        __syncthreads();
#pragma unroll
        for (int k = 0; k < 16; k++) {
            float a[4], b[4];
            *(float4*)a = *(const float4*)&As[k][ty * 4];
            *(float4*)b = *(const float4*)&Bs[k][tx * 4];
#pragma unroll
            for (int i = 0; i < 4; i++)
#pragma unroll
                for (int j = 0; j < 4; j++) acc[i][j] += a[i] * b[j];
        }
        __syncthreads();
    }

#pragma unroll
    for (int i = 0; i < 4; i++) {
        int mrow = bm + ty * 4 + i;
        float vals[4];
#pragma unroll
        for (int j = 0; j < 4; j++) {
            int ncol = bn + tx * 4 + j;
            vals[j] = acc[i][j] + bias[ncol];
        }
        if (mode == 2) {
            float ssq = vals[0]*vals[0] + vals[1]*vals[1] + vals[2]*vals[2] + vals[3]*vals[3];
#pragma unroll
            for (int o = 8; o; o >>= 1) ssq += __shfl_xor_sync(0xffffffffu, ssq, o);
            float sc = 1.0f / fmaxf(sqrtf(ssq), 1e-12f);
#pragma unroll
            for (int j = 0; j < 4; j++) vals[j] *= sc;
        }
#pragma unroll
        for (int j = 0; j < 4; j++) {
            int ncol = bn + tx * 4 + j;
            if (mode == 1) {
                int b = mrow >> 11, l = mrow & 2047, h = ncol >> 6, hd = ncol & 63;
                C[(((size_t)b * HH + h) * LL + l) * HD + hd] = vals[j];
            } else {
                C[(size_t)mrow * N + ncol] = vals[j];
            }
        }
    }
}

// ---------------- tiny 512->16 projection: Out[row,c] = X[row,:] @ Wbig[koff:koff+512, c]
__global__ void proj16_kernel(const float* __restrict__ X, const float* __restrict__ Wbig,
                              float* __restrict__ Out, int rows, int koff)
{
    int tg = blockIdx.x * blockDim.x + threadIdx.x;
    if (tg >= rows * EH) return;
    int c = tg & 15, row = tg >> 4;
    const float* x = X + (size_t)row * DD;
    const float* w = Wbig + (size_t)koff * EH + c;
    float a0 = 0.f, a1 = 0.f, a2 = 0.f, a3 = 0.f;
#pragma unroll 4
    for (int k = 0; k < DD; k += 4) {
        a0 += x[k + 0] * w[(size_t)(k + 0) * EH];
        a1 += x[k + 1] * w[(size_t)(k + 1) * EH];
        a2 += x[k + 2] * w[(size_t)(k + 2) * EH];
        a3 += x[k + 3] * w[(size_t)(k + 3) * EH];
    }
    Out[tg] = (a0 + a1) + (a2 + a3);
}

// ---------------- fused score + top-8 per (b,l) ----------------
__global__ __launch_bounds__(256) void score_topk_kernel(
    const float* __restrict__ bs1, const float* __restrict__ Ws2, const float* __restrict__ bs2)
{
    __shared__ float sc[KK];
    __shared__ float a16[EH];
    __shared__ float w2s[EH];
    __shared__ unsigned long long red[256];

    int b = blockIdx.x >> 11, l = blockIdx.x & 2047;
    int tid = threadIdx.x;
    if (tid < EH) {
        a16[tid] = g_SA[((size_t)b * LL + l) * EH + tid] + bs1[tid];
        w2s[tid] = Ws2[tid];
    }
    __syncthreads();
    float aR[EH], wR[EH];
#pragma unroll
    for (int c = 0; c < EH; c++) { aR[c] = a16[c]; wR[c] = w2s[c]; }
    float bs2v = bs2[0];

    for (int kk = tid; kk < KK; kk += 256) {
        const float4* bp = (const float4*)(g_SB + ((size_t)b * KK + kk) * EH);
        float4 b0 = bp[0], b1 = bp[1], b2 = bp[2], b3 = bp[3];
        float bv[EH] = {b0.x,b0.y,b0.z,b0.w, b1.x,b1.y,b1.z,b1.w,
                        b2.x,b2.y,b2.z,b2.w, b3.x,b3.y,b3.z,b3.w};
        float s = bs2v;
#pragma unroll
        for (int c = 0; c < EH; c++) s += geluf(aR[c] + bv[c]) * wR[c];
        sc[kk] = s;
    }
    __syncthreads();

    for (int w = 0; w < WWIN; w++) {
        unsigned long long best = 0ull;
        for (int kk = tid; kk < KK; kk += 256) {
            unsigned u = __float_as_uint(sc[kk]);
            u = (u & 0x80000000u) ? ~u : (u | 0x80000000u);
            unsigned long long key = (((unsigned long long)u) << 32) | (unsigned)(KK - 1 - kk);
            if (key > best) best = key;
        }
        red[tid] = best;
        __syncthreads();
        for (int s = 128; s > 0; s >>= 1) {
            if (tid < s && red[tid + s] > red[tid]) red[tid] = red[tid + s];
            __syncthreads();
        }
        if (tid == 0) {
            int idx = KK - 1 - (int)(red[0] & 0xffffffffu);
            g_idx[((size_t)b * LL + l) * WWIN + w] = idx;
            sc[idx] = __int_as_float(0xff800000);  // -inf
        }
        __syncthreads();
    }
}

// ---------------- per-edge small params: gh (for Lam GEMM), alpha, rope cos/sin ----------------
__global__ void edge_small_kernel(const float* __restrict__ bl1, const float* __restrict__ ba1,
                                  const float* __restrict__ Wa2, const float* __restrict__ ba2)
{
    int gw = (blockIdx.x * blockDim.x + threadIdx.x) >> 5;  // global warp = (b,e)
    int ln = threadIdx.x & 31;
    if (gw >= BB * EE) return;
    int b = gw >> 14, e = gw & (EE - 1);
    int l = e >> 3, w = e & 7;
    int j = g_idx[((size_t)b * LL + l) * WWIN + w];
    int i = l;

    float hav = 0.f;
    if (ln < EH) {
        int c = ln;
        float hl = g_LA[((size_t)b * LL + i) * EH + c] + g_LB[((size_t)b * KK + j) * EH + c] + bl1[c];
        g_gh[(size_t)gw * EH + c] = geluf(hl);
        float ha = g_AA[((size_t)b * LL + i) * EH + c] + g_AB[((size_t)b * KK + j) * EH + c] + ba1[c];
        hav = geluf(ha) * Wa2[c];
    }
#pragma unroll
    for (int o = 16; o; o >>= 1) hav += __shfl_xor_sync(0xffffffffu, hav, o);
    if (ln == 0) g_alpha[gw] = softplusf(hav + ba2[0]);

    // rope angles: inv_freq[t] = 10000^{-t/32} = exp2(-t * log2(10000)/32)
    float ang = (float)(i - j) * exp2f((float)ln * -0.41524101186092029f);
    g_cosv[(size_t)gw * 32 + ln] = cosf(ang);
    g_sinv[(size_t)gw * 32 + ln] = sinf(ang);
}

// ---------------- consensus iteration: block=(b,l), warp=head ----------------
__global__ __launch_bounds__(256) void iter_kernel(const float* __restrict__ step_sizes, int t)
{
    int b = blockIdx.x >> 11, l = blockIdx.x & 2047;
    int wi = threadIdx.x >> 5, ln = threadIdx.x & 31;

    size_t ubase = (((size_t)b * HH + wi) * LL + l) * HD;
    float u0 = g_u[ubase + ln];
    float u1 = g_u[ubase + 32 + ln];
    float acc0 = 0.f, acc1 = 0.f;
    float stp = softplusf(step_sizes[t * LL + l]);

    for (int w = 0; w < WWIN; w++) {
        int e = l * WWIN + w;
        size_t be = (size_t)b * EE + e;
        int j = g_idx[((size_t)b * LL + l) * WWIN + w];
        float cv = g_cosv[be * 32 + ln];
        float sv = g_sinv[be * 32 + ln];
        // rotate_half rope: out[:32] = u[:32]*c - u[32:]*s ; out[32:] = u[32:]*c + u[:32]*s
        float ui0 = u0 * cv - u1 * sv;
        float ui1 = u1 * cv + u0 * sv;

        size_t vbase = (((size_t)b * HH + wi) * KK + j) * HD;
        float d0 = ui0 - g_v[vbase + ln];
        float d1 = ui1 - g_v[vbase + 32 + ln];

        const float* lp = g_Lam + be * (HH * RR * HD) + (size_t)wi * (RR * HD);
        float l0[RR], l1[RR];
#pragma unroll
        for (int r = 0; r < RR; r++) {
            l0[r] = lp[r * HD + ln];
            l1[r] = lp[r * HD + 32 + ln];
        }
        float al = g_alpha[be];
        float r0 = al * d0, r1 = al * d1;
#pragma unroll
        for (int r = 0; r < RR; r++) {
            float p = l0[r] * d0 + l1[r] * d1;
#pragma unroll
            for (int o = 16; o; o >>= 1) p += __shfl_xor_sync(0xffffffffu, p, o);
            r0 += p * l0[r];
            r1 += p * l1[r];
        }
        acc0 += r0;
        acc1 += r1;
    }
    g_u[ubase + ln]      = u0 - stp * acc0;
    g_u[ubase + 32 + ln] = u1 - stp * acc1;
}

// ---------------- transpose [B,H,L,HD] -> [B,L,D] ----------------
__global__ void transpose_u_kernel()
{
    int o = blockIdx.x * blockDim.x + threadIdx.x;
    if (o >= BB * LL * DD) return;
    int d = o & 63, h = (o >> 6) & 7, l = (o >> 9) & 2047, b = o >> 20;
    g_ut[o] = g_u[(((size_t)b * HH + h) * LL + l) * HD + d];
}

// ---------------- launch ----------------
extern "C" void kernel_launch(void* const* d_in, const int* in_sizes, int n_in,
                              void* d_out, int out_size)
{
    const float* target = (const float*)d_in[0];
    const float* context= (const float*)d_in[1];
    const float* Wt  = (const float*)d_in[2];
    const float* bt  = (const float*)d_in[3];
    const float* Wc  = (const float*)d_in[4];
    const float* bc  = (const float*)d_in[5];
    const float* Ws1 = (const float*)d_in[6];
    const float* bs1 = (const float*)d_in[7];
    const float* Ws2 = (const float*)d_in[8];
    const float* bs2 = (const float*)d_in[9];
    const float* Wa1 = (const float*)d_in[10];
    const float* ba1 = (const float*)d_in[11];
    const float* Wa2 = (const float*)d_in[12];
    const float* ba2 = (const float*)d_in[13];
    const float* Wl1 = (const float*)d_in[14];
    const float* bl1 = (const float*)d_in[15];
    const float* Wl2 = (const float*)d_in[16];
    const float* bl2 = (const float*)d_in[17];
    const float* step_sizes = (const float*)d_in[18];
    const float* Wo  = (const float*)d_in[19];
    const float* bo  = (const float*)d_in[20];

    float *pu, *pv, *put, *pgh, *plam, *pSA, *pSB, *pAA, *pAB, *pLA, *pLB;
    cudaGetSymbolAddress((void**)&pu,  g_u);
    cudaGetSymbolAddress((void**)&pv,  g_v);
    cudaGetSymbolAddress((void**)&put, g_ut);
    cudaGetSymbolAddress((void**)&pgh, g_gh);
    cudaGetSymbolAddress((void**)&plam,g_Lam);
    cudaGetSymbolAddress((void**)&pSA, g_SA);
    cudaGetSymbolAddress((void**)&pSB, g_SB);
    cudaGetSymbolAddress((void**)&pAA, g_AA);
    cudaGetSymbolAddress((void**)&pAB, g_AB);
    cudaGetSymbolAddress((void**)&pLA, g_LA);
    cudaGetSymbolAddress((void**)&pLB, g_LB);

    const int Mrows = BB * LL;  // 4096

    // u = target@Wt+bt ; v = context@Wc+bc  (stored [B,H,*,HD])
    gemm_kernel<<<dim3(DD/64, Mrows/64), 256>>>(target,  Wt, bt, pu, Mrows, DD, DD, 1);
    gemm_kernel<<<dim3(DD/64, Mrows/64), 256>>>(context, Wc, bc, pv, Mrows, DD, DD, 1);

    // separable 16-dim projections for scorer / alpha MLP / Lam MLP
    int pthreads = Mrows * EH;
    int pblocks = (pthreads + 255) / 256;
    proj16_kernel<<<pblocks, 256>>>(target,  Ws1, pSA, Mrows, 0);
    proj16_kernel<<<pblocks, 256>>>(context, Ws1, pSB, Mrows, DD);
    proj16_kernel<<<pblocks, 256>>>(target,  Wa1, pAA, Mrows, 0);
    proj16_kernel<<<pblocks, 256>>>(context, Wa1, pAB, Mrows, DD);
    proj16_kernel<<<pblocks, 256>>>(target,  Wl1, pLA, Mrows, 0);
    proj16_kernel<<<pblocks, 256>>>(context, Wl1, pLB, Mrows, DD);

    // scores + top-8
    score_topk_kernel<<<BB * LL, 256>>>(bs1, Ws2, bs2);

    // per-edge small params
    edge_small_kernel<<<(BB * EE * 32 + 255) / 256, 256>>>(bl1, ba1, Wa2, ba2);

    // Lam = normalize_chunks( gh @ Wl2 + bl2 )  : M=32768, N=4096, K=16
    gemm_kernel<<<dim3((HH*RR*HD)/64, (BB*EE)/64), 256>>>(pgh, Wl2, bl2, plam,
                                                          BB*EE, HH*RR*HD, EH, 2);

    // T consensus iterations (in-place on g_u; rows independent)
    for (int t = 0; t < TT; t++)
        iter_kernel<<<BB * LL, 256>>>(step_sizes, t);

    // y = u^T @ Wo + bo
    transpose_u_kernel<<<(BB * LL * DD + 255) / 256, 256>>>();
    gemm_kernel<<<dim3(DD/64, Mrows/64), 256>>>(put, Wo, bo, (float*)d_out, Mrows, DD, DD, 0);
}

// round 2
// speedup vs baseline: 1.1604x; 1.1604x over previous
#include <cuda_runtime.h>
#include <cuda_fp16.h>
#include <cuda_bf16.h>
#include <cstdint>

// Problem constants
#define BB 2
#define LL 2048
#define KK 2048
#define DD 512
#define HH 8
#define HD 64
#define RR 8
#define WWIN 8
#define EE (LL*WWIN)          // 16384 edges per batch
#define EH 16
#define TT 2

// ---------------- scratch (allocation-free: static device globals) ----------------
__device__ float g_u [BB*HH*LL*HD];          // [B,H,L,HD]
__device__ float g_v [BB*HH*KK*HD];          // [B,H,K,HD]
__device__ float g_SA[BB*LL*EH];             // target @ Ws1[:D]
__device__ float g_SB[BB*KK*EH];             // context @ Ws1[D:]
__device__ float g_AA[BB*LL*EH];
__device__ float g_AB[BB*KK*EH];
__device__ float g_LA[BB*LL*EH];
__device__ float g_LB[BB*KK*EH];
__device__ int   g_idx[BB*LL*WWIN];
__device__ float g_gh[BB*EE*EH];             // gelu(h) per edge for Lam GEMM
__device__ float g_alpha[BB*EE];
__device__ __half g_LamH[(size_t)BB*EE*HH*RR*HD];  // 134M halves (256MB)

// ---------------- helpers ----------------
__device__ __forceinline__ float geluf(float x){
    return 0.5f * x * (1.0f + erff(x * 0.7071067811865475244f));
}
__device__ __forceinline__ float softplusf(float x){
    return (x > 20.f) ? x : log1pf(expf(x));
}

// ---------------- generic fp32 GEMM: C = A[MxK] @ W[KxN] + bias ----------------
// mode 0: C[m*N+n]
// mode 1: m=b*2048+l, n=h*64+hd -> C[((b*8+h)*2048+l)*64+hd]   (u/v layout)
// mode 2: normalize each 64-col chunk per row, store HALF into Ch
// mode 3: like mode 0 but A is read from u layout [B,H,L,HD] with m=(b,l), k=(h,hd)
__global__ __launch_bounds__(256) void gemm_kernel(
    const float* __restrict__ A, const float* __restrict__ W,
    const float* __restrict__ bias, float* __restrict__ C, __half* __restrict__ Ch,
    int M, int N, int Kd, int mode)
{
    __shared__ float As[16][68];
    __shared__ float Bs[16][64];
    const int bn = blockIdx.x * 64;
    const int bm = blockIdx.y * 64;
    const int tid = threadIdx.x;
    const int tx = tid & 15, ty = tid >> 4;

    float acc[4][4];
#pragma unroll
    for (int i = 0; i < 4; i++)
#pragma unroll
        for (int j = 0; j < 4; j++) acc[i][j] = 0.f;

    const int am = tid >> 2;
    const int akq = (tid & 3) * 4;
    const int bk = tid >> 4;
    const int bnq = (tid & 15) * 4;

    for (int k0 = 0; k0 < Kd; k0 += 16) {
        float4 av;
        if (mode == 3) {
            int mrow = bm + am;
            int b = mrow >> 11, l = mrow & 2047;
            int k = k0 + akq;
            int h = k >> 6, hd = k & 63;
            av = *(const float4*)&A[((((size_t)b * HH + h) * LL + l) * HD) + hd];
        } else {
            av = *(const float4*)&A[(size_t)(bm + am) * Kd + k0 + akq];
        }
        As[akq + 0][am] = av.x;
        As[akq + 1][am] = av.y;
        As[akq + 2][am] = av.z;
        As[akq + 3][am] = av.w;
        *(float4*)&Bs[bk][bnq] = *(const float4*)&W[(size_t)(k0 + bk) * N + bn + bnq];
        __syncthreads();
#pragma unroll
        for (int k = 0; k < 16; k++) {
            float a[4], b[4];
            *(float4*)a = *(const float4*)&As[k][ty * 4];
            *(float4*)b = *(const float4*)&Bs[k][tx * 4];
#pragma unroll
            for (int i = 0; i < 4; i++)
#pragma unroll
                for (int j = 0; j < 4; j++) acc[i][j] += a[i] * b[j];
        }
        __syncthreads();
    }

#pragma unroll
    for (int i = 0; i < 4; i++) {
        int mrow = bm + ty * 4 + i;
        float vals[4];
#pragma unroll
        for (int j = 0; j < 4; j++) {
            int ncol = bn + tx * 4 + j;
            vals[j] = acc[i][j] + bias[ncol];
        }
        if (mode == 2) {
            float ssq = vals[0]*vals[0] + vals[1]*vals[1] + vals[2]*vals[2] + vals[3]*vals[3];
#pragma unroll
            for (int o = 8; o; o >>= 1) ssq += __shfl_xor_sync(0xffffffffu, ssq, o);
            float sc = 1.0f / fmaxf(sqrtf(ssq), 1e-12f);
            size_t base = (size_t)mrow * N + bn + tx * 4;
            __half2 h01 = __floats2half2_rn(vals[0] * sc, vals[1] * sc);
            __half2 h23 = __floats2half2_rn(vals[2] * sc, vals[3] * sc);
            *(__half2*)&Ch[base]     = h01;
            *(__half2*)&Ch[base + 2] = h23;
        } else {
#pragma unroll
            for (int j = 0; j < 4; j++) {
                int ncol = bn + tx * 4 + j;
                if (mode == 1) {
                    int b = mrow >> 11, l = mrow & 2047, h = ncol >> 6, hd = ncol & 63;
                    C[(((size_t)b * HH + h) * LL + l) * HD + hd] = vals[j];
                } else {
                    C[(size_t)mrow * N + ncol] = vals[j];
                }
            }
        }
    }
}

// ---------------- fused 512->48 projection: three [512,16] weights at once ------
// Block: 64 rows x 48 cols. Reads X once, outputs into three [rows,16] arrays.
__global__ __launch_bounds__(256) void proj_fused_kernel(
    const float* __restrict__ X,
    const float* __restrict__ W1, const float* __restrict__ W2, const float* __restrict__ W3,
    float* __restrict__ O1, float* __restrict__ O2, float* __restrict__ O3,
    int koff)
{
    __shared__ float Xs[64][68];
    __shared__ float Ws[64][52];
    const int row0 = blockIdx.x * 64;
    const int tid = threadIdx.x;
    const int r = tid >> 2;
    const int c0 = (tid & 3) * 12;

    float acc[12];
#pragma unroll
    for (int j = 0; j < 12; j++) acc[j] = 0.f;

    for (int k0 = 0; k0 < DD; k0 += 64) {
        // X tile: 64 rows x 64 cols
#pragma unroll
        for (int i = 0; i < 4; i++) {
            int idx = tid + i * 256;
            int rr = idx >> 4, q = (idx & 15) * 4;
            *(float4*)&Xs[rr][q] = *(const float4*)&X[(size_t)(row0 + rr) * DD + k0 + q];
        }
        // W tiles: 64 rows x 16 cols each
        {
            int kr = tid >> 2, q = (tid & 3) * 4;
            *(float4*)&Ws[kr][ 0 + q] = *(const float4*)&W1[(size_t)(koff + k0 + kr) * EH + q];
            *(float4*)&Ws[kr][16 + q] = *(const float4*)&W2[(size_t)(koff + k0 + kr) * EH + q];
            *(float4*)&Ws[kr][32 + q] = *(const float4*)&W3[(size_t)(koff + k0 + kr) * EH + q];
        }
        __syncthreads();
#pragma unroll
        for (int k = 0; k < 64; k++) {
            float x = Xs[r][k];
            float4 w0 = *(const float4*)&Ws[k][c0];
            float4 w1 = *(const float4*)&Ws[k][c0 + 4];
            float4 w2 = *(const float4*)&Ws[k][c0 + 8];
            acc[0] += x * w0.x;  acc[1] += x * w0.y;  acc[2]  += x * w0.z;  acc[3]  += x * w0.w;
            acc[4] += x * w1.x;  acc[5] += x * w1.y;  acc[6]  += x * w1.z;  acc[7]  += x * w1.w;
            acc[8] += x * w2.x;  acc[9] += x * w2.y;  acc[10] += x * w2.z;  acc[11] += x * w2.w;
        }
        __syncthreads();
    }

    const int row = row0 + r;
#pragma unroll
    for (int j = 0; j < 12; j++) {
        int c = c0 + j;
        int m = c >> 4, cc = c & 15;
        float* O = (m == 0) ? O1 : (m == 1) ? O2 : O3;
        O[(size_t)row * EH + cc] = acc[j];
    }
}

// ---------------- fused score + top-8 per (b,l) ----------------
__global__ __launch_bounds__(256) void score_topk_kernel(
    const float* __restrict__ bs1, const float* __restrict__ Ws2, const float* __restrict__ bs2)
{
    __shared__ float sc[KK];
    __shared__ float a16[EH];
    __shared__ float w2s[EH];
    __shared__ unsigned long long red[256];

    int b = blockIdx.x >> 11, l = blockIdx.x & 2047;
    int tid = threadIdx.x;
    if (tid < EH) {
        a16[tid] = g_SA[((size_t)b * LL + l) * EH + tid] + bs1[tid];
        w2s[tid] = Ws2[tid];
    }
    __syncthreads();
    float aR[EH], wR[EH];
#pragma unroll
    for (int c = 0; c < EH; c++) { aR[c] = a16[c]; wR[c] = w2s[c]; }
    float bs2v = bs2[0];

    for (int kk = tid; kk < KK; kk += 256) {
        const float4* bp = (const float4*)(g_SB + ((size_t)b * KK + kk) * EH);
        float4 b0 = bp[0], b1 = bp[1], b2 = bp[2], b3 = bp[3];
        float bv[EH] = {b0.x,b0.y,b0.z,b0.w, b1.x,b1.y,b1.z,b1.w,
                        b2.x,b2.y,b2.z,b2.w, b3.x,b3.y,b3.z,b3.w};
        float s = bs2v;
#pragma unroll
        for (int c = 0; c < EH; c++) s += geluf(aR[c] + bv[c]) * wR[c];
        sc[kk] = s;
    }
    __syncthreads();

    for (int w = 0; w < WWIN; w++) {
        unsigned long long best = 0ull;
        for (int kk = tid; kk < KK; kk += 256) {
            unsigned u = __float_as_uint(sc[kk]);
            u = (u & 0x80000000u) ? ~u : (u | 0x80000000u);
            unsigned long long key = (((unsigned long long)u) << 32) | (unsigned)(KK - 1 - kk);
            if (key > best) best = key;
        }
        red[tid] = best;
        __syncthreads();
        for (int s = 128; s > 0; s >>= 1) {
            if (tid < s && red[tid + s] > red[tid]) red[tid] = red[tid + s];
            __syncthreads();
        }
        if (tid == 0) {
            int idx = KK - 1 - (int)(red[0] & 0xffffffffu);
            g_idx[((size_t)b * LL + l) * WWIN + w] = idx;
            sc[idx] = __int_as_float(0xff800000);  // -inf
        }
        __syncthreads();
    }
}

// ---------------- per-edge small params: gh (for Lam GEMM), alpha ----------------
__global__ void edge_small_kernel(const float* __restrict__ bl1, const float* __restrict__ ba1,
                                  const float* __restrict__ Wa2, const float* __restrict__ ba2)
{
    int gw = (blockIdx.x * blockDim.x + threadIdx.x) >> 5;  // global warp = (b,e)
    int ln = threadIdx.x & 31;
    if (gw >= BB * EE) return;
    int b = gw >> 14, e = gw & (EE - 1);
    int l = e >> 3, w = e & 7;
    int j = g_idx[((size_t)b * LL + l) * WWIN + w];
    int i = l;

    float hav = 0.f;
    if (ln < EH) {
        int c = ln;
        float hl = g_LA[((size_t)b * LL + i) * EH + c] + g_LB[((size_t)b * KK + j) * EH + c] + bl1[c];
        g_gh[(size_t)gw * EH + c] = geluf(hl);
        float ha = g_AA[((size_t)b * LL + i) * EH + c] + g_AB[((size_t)b * KK + j) * EH + c] + ba1[c];
        hav = geluf(ha) * Wa2[c];
    }
#pragma unroll
    for (int o = 16; o; o >>= 1) hav += __shfl_xor_sync(0xffffffffu, hav, o);
    if (ln == 0) g_alpha[gw] = softplusf(hav + ba2[0]);
}

// ---------------- fused T=2 consensus iterations: block=(b,l), warp=head --------
// Rows are independent (edge_i == l), so u lives in registers across both
// iterations. Lam (fp16, 64KB) + gathered v (16KB) are staged in dynamic smem.
#define ITER_DYN_SMEM (8*HH*RR*HD*2 + 8*HH*HD*4)   // 65536 + 16384 = 81920 B
__global__ __launch_bounds__(256) void iter2_kernel(const float* __restrict__ step_sizes)
{
    extern __shared__ char dyn[];
    __half* s_lam = (__half*)dyn;                        // [8][H][R][HD]
    float*  s_v   = (float*)(dyn + 8*HH*RR*HD*2);        // [8][H][HD]
    __shared__ float s_cs[8][32];
    __shared__ float s_sn[8][32];
    __shared__ float s_alpha[8];
    __shared__ int   s_idx[8];

    int b = blockIdx.x >> 11, l = blockIdx.x & 2047;
    int tid = threadIdx.x;
    int wi = tid >> 5, ln = tid & 31;

    // stage Lam: contiguous 8*4096 halves per (b,l)
    {
        const float4* src = (const float4*)(g_LamH + ((size_t)b * EE + (size_t)l * 8) * (HH*RR*HD));
        float4* dst = (float4*)s_lam;
#pragma unroll
        for (int i = 0; i < 16; i++) dst[tid + i * 256] = src[tid + i * 256];
    }
    // edge metadata + rope angles (warp wi handles edge e = wi)
    {
        int e = wi;
        int j = g_idx[((size_t)b * LL + l) * WWIN + e];
        if (ln == 0) {
            s_idx[e] = j;
            s_alpha[e] = g_alpha[(size_t)b * EE + l * WWIN + e];
        }
        float ang = (float)(l - j) * exp2f((float)ln * -0.41524101186092029f);
        s_cs[e][ln] = cosf(ang);
        s_sn[e][ln] = sinf(ang);
    }
    __syncthreads();
    // stage gathered v rows: [e][h][64]
#pragma unroll
    for (int i = 0; i < 16; i++) {
        int gid = tid + i * 256;           // 0..4095
        int e2 = gid >> 9, h2 = (gid >> 6) & 7, d = gid & 63;
        s_v[gid] = g_v[(((size_t)b * HH + h2) * KK + s_idx[e2]) * HD + d];
    }
    __syncthreads();

    size_t ubase = (((size_t)b * HH + wi) * LL + l) * HD;
    float u0 = g_u[ubase + ln];
    float u1 = g_u[ubase + 32 + ln];

#pragma unroll
    for (int t = 0; t < TT; t++) {
        float stp = softplusf(step_sizes[t * LL + l]);
        float acc0 = 0.f, acc1 = 0.f;
#pragma unroll
        for (int e = 0; e < WWIN; e++) {
            float cv = s_cs[e][ln], sv = s_sn[e][ln];
            float ui0 = u0 * cv - u1 * sv;
            float ui1 = u1 * cv + u0 * sv;
            float d0 = ui0 - s_v[(e * HH + wi) * HD + ln];
            float d1 = ui1 - s_v[(e * HH + wi) * HD + 32 + ln];
            float al = s_alpha[e];
            float r0 = al * d0, r1 = al * d1;
            const __half* lp = s_lam + ((e * HH + wi) * RR) * HD;
#pragma unroll
            for (int r = 0; r < RR; r++) {
                float l0 = __half2float(lp[r * HD + ln]);
                float l1 = __half2float(lp[r * HD + 32 + ln]);
                float p = l0 * d0 + l1 * d1;
#pragma unroll
                for (int o = 16; o; o >>= 1) p += __shfl_xor_sync(0xffffffffu, p, o);
                r0 += p * l0;
                r1 += p * l1;
            }
            acc0 += r0;
            acc1 += r1;
        }
        u0 -= stp * acc0;
        u1 -= stp * acc1;
    }
    g_u[ubase + ln]      = u0;
    g_u[ubase + 32 + ln] = u1;
}

// ---------------- launch ----------------
extern "C" void kernel_launch(void* const* d_in, const int* in_sizes, int n_in,
                              void* d_out, int out_size)
{
    const float* target = (const float*)d_in[0];
    const float* context= (const float*)d_in[1];
    const float* Wt  = (const float*)d_in[2];
    const float* bt  = (const float*)d_in[3];
    const float* Wc  = (const float*)d_in[4];
    const float* bc  = (const float*)d_in[5];
    const float* Ws1 = (const float*)d_in[6];
    const float* bs1 = (const float*)d_in[7];
    const float* Ws2 = (const float*)d_in[8];
    const float* bs2 = (const float*)d_in[9];
    const float* Wa1 = (const float*)d_in[10];
    const float* ba1 = (const float*)d_in[11];
    const float* Wa2 = (const float*)d_in[12];
    const float* ba2 = (const float*)d_in[13];
    const float* Wl1 = (const float*)d_in[14];
    const float* bl1 = (const float*)d_in[15];
    const float* Wl2 = (const float*)d_in[16];
    const float* bl2 = (const float*)d_in[17];
    const float* step_sizes = (const float*)d_in[18];
    const float* Wo  = (const float*)d_in[19];
    const float* bo  = (const float*)d_in[20];

    float *pu, *pv, *pgh, *pSA, *pSB, *pAA, *pAB, *pLA, *pLB;
    __half* plamh;
    cudaGetSymbolAddress((void**)&pu,   g_u);
    cudaGetSymbolAddress((void**)&pv,   g_v);
    cudaGetSymbolAddress((void**)&pgh,  g_gh);
    cudaGetSymbolAddress((void**)&plamh,g_LamH);
    cudaGetSymbolAddress((void**)&pSA,  g_SA);
    cudaGetSymbolAddress((void**)&pSB,  g_SB);
    cudaGetSymbolAddress((void**)&pAA,  g_AA);
    cudaGetSymbolAddress((void**)&pAB,  g_AB);
    cudaGetSymbolAddress((void**)&pLA,  g_LA);
    cudaGetSymbolAddress((void**)&pLB,  g_LB);

    cudaFuncSetAttribute(iter2_kernel, cudaFuncAttributeMaxDynamicSharedMemorySize,
                         ITER_DYN_SMEM);

    const int Mrows = BB * LL;  // 4096

    // u = target@Wt+bt ; v = context@Wc+bc  (stored [B,H,*,HD])
    gemm_kernel<<<dim3(DD/64, Mrows/64), 256>>>(target,  Wt, bt, pu, nullptr, Mrows, DD, DD, 1);
    gemm_kernel<<<dim3(DD/64, Mrows/64), 256>>>(context, Wc, bc, pv, nullptr, Mrows, DD, DD, 1);

    // separable 16-dim projections (3 weights per side, one pass over X each)
    proj_fused_kernel<<<Mrows/64, 256>>>(target,  Ws1, Wa1, Wl1, pSA, pAA, pLA, 0);
    proj_fused_kernel<<<Mrows/64, 256>>>(context, Ws1, Wa1, Wl1, pSB, pAB, pLB, DD);

    // scores + top-8
    score_topk_kernel<<<BB * LL, 256>>>(bs1, Ws2, bs2);

    // per-edge small params
    edge_small_kernel<<<(BB * EE * 32 + 255) / 256, 256>>>(bl1, ba1, Wa2, ba2);

    // Lam(fp16) = normalize_chunks( gh @ Wl2 + bl2 )  : M=32768, N=4096, K=16
    gemm_kernel<<<dim3((HH*RR*HD)/64, (BB*EE)/64), 256>>>(pgh, Wl2, bl2, nullptr, plamh,
                                                          BB*EE, HH*RR*HD, EH, 2);

    // both consensus iterations fused (u in registers, Lam/v staged in smem)
    iter2_kernel<<<BB * LL, 256, ITER_DYN_SMEM>>>(step_sizes);

    // y = u^T @ Wo + bo   (transpose folded into A-loader, mode 3)
    gemm_kernel<<<dim3(DD/64, Mrows/64), 256>>>(pu, Wo, bo, (float*)d_out, nullptr,
                                                Mrows, DD, DD, 3);
}

// round 3
// speedup vs baseline: 1.5994x; 1.3783x over previous
#include <cuda_runtime.h>
#include <cuda_fp16.h>
#include <cstdint>

// Problem constants
#define BB 2
#define LL 2048
#define KK 2048
#define DD 512
#define HH 8
#define HD 64
#define RR 8
#define WWIN 8
#define EE (LL*WWIN)          // 16384 edges per batch
#define EH 16
#define TT 2
#define NLAM (HH*RR*HD)       // 4096

// ---------------- scratch (allocation-free: static device globals) ----------------
__device__ float  g_u [BB*HH*LL*HD];          // [B,H,L,HD]
__device__ float  g_v [BB*HH*KK*HD];          // [B,H,K,HD]
__device__ float  g_SA[BB*LL*EH];
__device__ float  g_SB[BB*KK*EH];
__device__ float  g_AA[BB*LL*EH];
__device__ float  g_AB[BB*KK*EH];
__device__ float  g_LA[BB*LL*EH];
__device__ float  g_LB[BB*KK*EH];
__device__ int    g_idx[BB*LL*WWIN];
__device__ __half g_gh[BB*EE*EH];             // gelu(h) per edge, fp16 (A of Lam mma)
__device__ float  g_alpha[BB*EE];
__device__ __half g_Wl2h[NLAM*EH];            // Wl2 transposed [n][k] fp16
__device__ __half g_LamH[(size_t)BB*EE*NLAM]; // 256MB

// ---------------- helpers ----------------
__device__ __forceinline__ float geluf(float x){
    return 0.5f * x * (1.0f + erff(x * 0.7071067811865475244f));
}
__device__ __forceinline__ float softplusf(float x){
    return (x > 20.f) ? x : log1pf(expf(x));
}
__device__ __forceinline__ float tf32_rna(float x){
    uint32_t u;
    asm("cvt.rna.tf32.f32 %0, %1;" : "=r"(u) : "f"(x));
    return __uint_as_float(u);
}
__device__ __forceinline__ void mma_tf32(float* d, const uint32_t* a, const uint32_t* b){
    asm("mma.sync.aligned.m16n8k8.row.col.f32.tf32.tf32.f32 "
        "{%0,%1,%2,%3}, {%4,%5,%6,%7}, {%8,%9}, {%0,%1,%2,%3};"
        : "+f"(d[0]), "+f"(d[1]), "+f"(d[2]), "+f"(d[3])
        : "r"(a[0]), "r"(a[1]), "r"(a[2]), "r"(a[3]), "r"(b[0]), "r"(b[1]));
}
__device__ __forceinline__ void mma_f16(float* d, uint32_t a0, uint32_t a1, uint32_t a2,
                                        uint32_t a3, uint32_t b0, uint32_t b1){
    asm("mma.sync.aligned.m16n8k16.row.col.f32.f16.f16.f32 "
        "{%0,%1,%2,%3}, {%4,%5,%6,%7}, {%8,%9}, {%0,%1,%2,%3};"
        : "+f"(d[0]), "+f"(d[1]), "+f"(d[2]), "+f"(d[3])
        : "r"(a0), "r"(a1), "r"(a2), "r"(a3), "r"(b0), "r"(b1));
}

// ---------------- tf32 tensor-core GEMM: C = A[MxK] @ W[KxN] + bias ----------------
// aload: 0 = A row-major [M][K]; 1 = A gathered from u layout [B,H,L,HD], m=(b,l), k=(h,hd)
// smode: 0 = plain C[m*N+n];     1 = store to u/v layout [B,H,*,HD]
__global__ __launch_bounds__(256) void gemm32_kernel(
    const float* __restrict__ A, const float* __restrict__ W,
    const float* __restrict__ bias, float* __restrict__ C,
    int M, int N, int Kd, int aload, int smode)
{
    __shared__ float As[128][36];
    __shared__ float Bs[32][72];
    const int bm = blockIdx.y * 128;
    const int bn = blockIdx.x * 64;
    const int tid  = threadIdx.x;
    const int warp = tid >> 5, lane = tid & 31;
    const int wm = warp & 3, wn = warp >> 2;
    const int q = lane >> 2, c = lane & 3;

    float d[2][4][4];
#pragma unroll
    for (int mt = 0; mt < 2; mt++)
#pragma unroll
        for (int nt = 0; nt < 4; nt++)
#pragma unroll
            for (int i = 0; i < 4; i++) d[mt][nt][i] = 0.f;

    for (int k0 = 0; k0 < Kd; k0 += 32) {
        // stage A (128x32), tf32-rounded
#pragma unroll
        for (int i = 0; i < 4; i++) {
            int id = tid + i * 256;
            int m = id >> 3, kq = (id & 7) * 4;
            float4 v;
            if (aload) {
                int mm = bm + m; int b = mm >> 11, l = mm & 2047;
                int k = k0 + kq; int h = k >> 6, hd = k & 63;
                v = *(const float4*)&A[(((size_t)b * HH + h) * LL + l) * HD + hd];
            } else {
                v = *(const float4*)&A[(size_t)(bm + m) * Kd + k0 + kq];
            }
            float4 t = make_float4(tf32_rna(v.x), tf32_rna(v.y), tf32_rna(v.z), tf32_rna(v.w));
            *(float4*)&As[m][kq] = t;
        }
        // stage B (32x64), tf32-rounded
#pragma unroll
        for (int i = 0; i < 2; i++) {
            int id = tid + i * 256;
            int kk = id >> 4, nq = (id & 15) * 4;
            float4 v = *(const float4*)&W[(size_t)(k0 + kk) * N + bn + nq];
            float4 t = make_float4(tf32_rna(v.x), tf32_rna(v.y), tf32_rna(v.z), tf32_rna(v.w));
            *(float4*)&Bs[kk][nq] = t;
        }
        __syncthreads();
#pragma unroll
        for (int k8 = 0; k8 < 4; k8++) {
            uint32_t a[2][4], b[4][2];
#pragma unroll
            for (int mt = 0; mt < 2; mt++) {
                int r0 = wm * 32 + mt * 16 + q;
                a[mt][0] = __float_as_uint(As[r0    ][k8 * 8 + c]);
                a[mt][1] = __float_as_uint(As[r0 + 8][k8 * 8 + c]);
                a[mt][2] = __float_as_uint(As[r0    ][k8 * 8 + c + 4]);
                a[mt][3] = __float_as_uint(As[r0 + 8][k8 * 8 + c + 4]);
            }
#pragma unroll
            for (int nt = 0; nt < 4; nt++) {
                int cn = wn * 32 + nt * 8 + q;
                b[nt][0] = __float_as_uint(Bs[k8 * 8 + c    ][cn]);
                b[nt][1] = __float_as_uint(Bs[k8 * 8 + c + 4][cn]);
            }
#pragma unroll
            for (int mt = 0; mt < 2; mt++)
#pragma unroll
                for (int nt = 0; nt < 4; nt++)
                    mma_tf32(d[mt][nt], a[mt], b[nt]);
        }
        __syncthreads();
    }

#pragma unroll
    for (int mt = 0; mt < 2; mt++) {
        int gm0 = bm + wm * 32 + mt * 16 + q;
#pragma unroll
        for (int nt = 0; nt < 4; nt++) {
            int gn = bn + wn * 32 + nt * 8 + 2 * c;
            float b0 = __ldg(&bias[gn]), b1 = __ldg(&bias[gn + 1]);
            float v0 = d[mt][nt][0] + b0, v1 = d[mt][nt][1] + b1;
            float v2 = d[mt][nt][2] + b0, v3 = d[mt][nt][3] + b1;
            if (smode == 1) {
                int bb = gm0 >> 11, l = gm0 & 2047, h = gn >> 6, hd = gn & 63;
                float* p0 = &C[(((size_t)bb * HH + h) * LL + l) * HD + hd];
                p0[0] = v0; p0[1] = v1;
                float* p2 = &C[(((size_t)bb * HH + h) * LL + (l + 8)) * HD + hd];
                p2[0] = v2; p2[1] = v3;
            } else {
                float2 lo = make_float2(v0, v1), hi = make_float2(v2, v3);
                *(float2*)&C[(size_t)gm0 * N + gn] = lo;
                *(float2*)&C[(size_t)(gm0 + 8) * N + gn] = hi;
            }
        }
    }
}

// ---------------- Wl2 transpose+convert: [16][4096] f32 -> [4096][16] f16 ----------
__global__ void prep_wl2_kernel(const float* __restrict__ Wl2)
{
    int n = blockIdx.x * blockDim.x + threadIdx.x;
    if (n >= NLAM) return;
#pragma unroll
    for (int k = 0; k < EH; k++)
        g_Wl2h[n * EH + k] = __float2half(Wl2[(size_t)k * NLAM + n]);
}

// ---------------- Lam fp16 MMA + fused chunk-normalization ------------------------
// Lam[m][n] = normalize_64chunk( gh[m][:16] @ Wl2h[:16][n] + bl2[n] ), store fp16
__global__ __launch_bounds__(256) void lam_mma_kernel(const float* __restrict__ bl2)
{
    __shared__ __half Ws[64][24];   // pitch 24 halves (48B) -> conflict-free
    __shared__ float  Wb[64];
    const int n0 = blockIdx.x * 64;
    const int m0 = blockIdx.y * 128;
    const int tid = threadIdx.x;
    const int warp = tid >> 5, lane = tid & 31;
    const int q = lane >> 2, c = lane & 3;

    if (tid < 128) {
        int nl = tid >> 1, part = tid & 1;
        *(int4*)&Ws[nl][part * 8] = *(const int4*)&g_Wl2h[(size_t)(n0 + nl) * EH + part * 8];
    }
    if (tid < 64) Wb[tid] = bl2[n0 + tid];
    __syncthreads();

    const int ra = m0 + warp * 16 + q;
    const uint32_t* ar0 = (const uint32_t*)&g_gh[(size_t)ra * EH];
    const uint32_t* ar1 = (const uint32_t*)&g_gh[(size_t)(ra + 8) * EH];
    uint32_t a0 = ar0[c], a1 = ar1[c], a2 = ar0[c + 4], a3 = ar1[c + 4];

    float d[8][4];
#pragma unroll
    for (int nt = 0; nt < 8; nt++) { d[nt][0]=d[nt][1]=d[nt][2]=d[nt][3]=0.f; }
#pragma unroll
    for (int nt = 0; nt < 8; nt++) {
        int nl = nt * 8 + q;
        uint32_t b0 = *(const uint32_t*)&Ws[nl][2 * c];
        uint32_t b1 = *(const uint32_t*)&Ws[nl][2 * c + 8];
        mma_f16(d[nt], a0, a1, a2, a3, b0, b1);
    }

    float s0 = 0.f, s1 = 0.f;
#pragma unroll
    for (int nt = 0; nt < 8; nt++) {
        float bA = Wb[nt * 8 + 2 * c], bB = Wb[nt * 8 + 2 * c + 1];
        d[nt][0] += bA; d[nt][1] += bB; d[nt][2] += bA; d[nt][3] += bB;
        s0 += d[nt][0] * d[nt][0] + d[nt][1] * d[nt][1];
        s1 += d[nt][2] * d[nt][2] + d[nt][3] * d[nt][3];
    }
    s0 += __shfl_xor_sync(0xffffffffu, s0, 1); s0 += __shfl_xor_sync(0xffffffffu, s0, 2);
    s1 += __shfl_xor_sync(0xffffffffu, s1, 1); s1 += __shfl_xor_sync(0xffffffffu, s1, 2);
    float sc0 = 1.f / fmaxf(sqrtf(s0), 1e-12f);
    float sc1 = 1.f / fmaxf(sqrtf(s1), 1e-12f);
#pragma unroll
    for (int nt = 0; nt < 8; nt++) {
        int col = n0 + nt * 8 + 2 * c;
        *(__half2*)&g_LamH[(size_t)ra * NLAM + col] =
            __floats2half2_rn(d[nt][0] * sc0, d[nt][1] * sc0);
        *(__half2*)&g_LamH[(size_t)(ra + 8) * NLAM + col] =
            __floats2half2_rn(d[nt][2] * sc1, d[nt][3] * sc1);
    }
}

// ---------------- fused 512->48 projection (both inputs, 32-row tiles) -------------
__global__ __launch_bounds__(256) void proj_fused_kernel(
    const float* __restrict__ Xt, const float* __restrict__ Xc,
    const float* __restrict__ W1, const float* __restrict__ W2, const float* __restrict__ W3,
    float* __restrict__ O1t, float* __restrict__ O2t, float* __restrict__ O3t,
    float* __restrict__ O1c, float* __restrict__ O2c, float* __restrict__ O3c)
{
    __shared__ float Xs[32][68];
    __shared__ float Ws[64][52];
    const int sel = blockIdx.x >> 7;
    const float* X = sel ? Xc : Xt;
    const int koff = sel ? DD : 0;
    const int row0 = (blockIdx.x & 127) * 32;
    const int tid = threadIdx.x;
    const int r = tid >> 3, c0 = (tid & 7) * 6;

    float acc[6] = {0.f, 0.f, 0.f, 0.f, 0.f, 0.f};

    for (int k0 = 0; k0 < DD; k0 += 64) {
#pragma unroll
        for (int i = 0; i < 2; i++) {
            int id = tid + i * 256;
            int rr = id >> 4, qq = (id & 15) * 4;
            *(float4*)&Xs[rr][qq] = *(const float4*)&X[(size_t)(row0 + rr) * DD + k0 + qq];
        }
        {
            int kr = tid >> 2, qq = (tid & 3) * 4;
            *(float4*)&Ws[kr][ 0 + qq] = *(const float4*)&W1[(size_t)(koff + k0 + kr) * EH + qq];
            *(float4*)&Ws[kr][16 + qq] = *(const float4*)&W2[(size_t)(koff + k0 + kr) * EH + qq];
            *(float4*)&Ws[kr][32 + qq] = *(const float4*)&W3[(size_t)(koff + k0 + kr) * EH + qq];
        }
        __syncthreads();
#pragma unroll
        for (int k = 0; k < 64; k++) {
            float x = Xs[r][k];
            float2 w01 = *(const float2*)&Ws[k][c0];
            float2 w23 = *(const float2*)&Ws[k][c0 + 2];
            float2 w45 = *(const float2*)&Ws[k][c0 + 4];
            acc[0] += x * w01.x; acc[1] += x * w01.y;
            acc[2] += x * w23.x; acc[3] += x * w23.y;
            acc[4] += x * w45.x; acc[5] += x * w45.y;
        }
        __syncthreads();
    }

    const int row = row0 + r;
#pragma unroll
    for (int j = 0; j < 6; j++) {
        int cc = c0 + j;
        int m = cc >> 4, col = cc & 15;
        float* O = sel ? (m == 0 ? O1c : m == 1 ? O2c : O3c)
                       : (m == 0 ? O1t : m == 1 ? O2t : O3t);
        O[(size_t)row * EH + col] = acc[j];
    }
}

// ---------------- fused score + top-8 per (b,l) ----------------
__global__ __launch_bounds__(256) void score_topk_kernel(
    const float* __restrict__ bs1, const float* __restrict__ Ws2, const float* __restrict__ bs2)
{
    __shared__ float sc[KK];
    __shared__ float a16[EH];
    __shared__ float w2s[EH];
    __shared__ unsigned long long wred[8];

    int b = blockIdx.x >> 11, l = blockIdx.x & 2047;
    int tid = threadIdx.x;
    int warp = tid >> 5, lane = tid & 31;
    if (tid < EH) {
        a16[tid] = g_SA[((size_t)b * LL + l) * EH + tid] + bs1[tid];
        w2s[tid] = Ws2[tid];
    }
    __syncthreads();
    float aR[EH], wR[EH];
#pragma unroll
    for (int c = 0; c < EH; c++) { aR[c] = a16[c]; wR[c] = w2s[c]; }
    float bs2v = bs2[0];

    for (int kk = tid; kk < KK; kk += 256) {
        const float4* bp = (const float4*)(g_SB + ((size_t)b * KK + kk) * EH);
        float4 b0 = bp[0], b1 = bp[1], b2 = bp[2], b3 = bp[3];
        float bv[EH] = {b0.x,b0.y,b0.z,b0.w, b1.x,b1.y,b1.z,b1.w,
                        b2.x,b2.y,b2.z,b2.w, b3.x,b3.y,b3.z,b3.w};
        float s = bs2v;
#pragma unroll
        for (int c = 0; c < EH; c++) s += geluf(aR[c] + bv[c]) * wR[c];
        sc[kk] = s;
    }
    __syncthreads();

    for (int w = 0; w < WWIN; w++) {
        unsigned long long best = 0ull;
#pragma unroll
        for (int i = 0; i < KK / 256; i++) {
            int kk = tid + i * 256;
            unsigned u = __float_as_uint(sc[kk]);
            u = (u & 0x80000000u) ? ~u : (u | 0x80000000u);
            unsigned long long key = (((unsigned long long)u) << 32) | (unsigned)(KK - 1 - kk);
            if (key > best) best = key;
        }
#pragma unroll
        for (int o = 16; o; o >>= 1) {
            unsigned long long other = __shfl_xor_sync(0xffffffffu, best, o);
            if (other > best) best = other;
        }
        if (lane == 0) wred[warp] = best;
        __syncthreads();
        if (tid == 0) {
            unsigned long long top = wred[0];
#pragma unroll
            for (int i = 1; i < 8; i++) if (wred[i] > top) top = wred[i];
            int idx = KK - 1 - (int)(top & 0xffffffffu);
            g_idx[((size_t)b * LL + l) * WWIN + w] = idx;
            sc[idx] = __int_as_float(0xff800000);  // -inf
        }
        __syncthreads();
    }
}

// ---------------- per-edge small params: gh (fp16), alpha ----------------
__global__ void edge_small_kernel(const float* __restrict__ bl1, const float* __restrict__ ba1,
                                  const float* __restrict__ Wa2, const float* __restrict__ ba2)
{
    int gw = (blockIdx.x * blockDim.x + threadIdx.x) >> 5;  // global warp = (b,e)
    int ln = threadIdx.x & 31;
    if (gw >= BB * EE) return;
    int b = gw >> 14, e = gw & (EE - 1);
    int l = e >> 3, w = e & 7;
    int j = g_idx[((size_t)b * LL + l) * WWIN + w];
    int i = l;

    float hav = 0.f;
    if (ln < EH) {
        int c = ln;
        float hl = g_LA[((size_t)b * LL + i) * EH + c] + g_LB[((size_t)b * KK + j) * EH + c] + bl1[c];
        g_gh[(size_t)gw * EH + c] = __float2half(geluf(hl));
        float ha = g_AA[((size_t)b * LL + i) * EH + c] + g_AB[((size_t)b * KK + j) * EH + c] + ba1[c];
        hav = geluf(ha) * Wa2[c];
    }
#pragma unroll
    for (int o = 16; o; o >>= 1) hav += __shfl_xor_sync(0xffffffffu, hav, o);
    if (ln == 0) g_alpha[gw] = softplusf(hav + ba2[0]);
}

// ---------------- fused T=2 consensus iterations: block=(b,l), warp=head --------
#define ITER_DYN_SMEM (8*HH*RR*HD*2 + 8*HH*HD*4)   // 65536 + 16384 = 81920 B
__global__ __launch_bounds__(256) void iter2_kernel(const float* __restrict__ step_sizes)
{
    extern __shared__ char dyn[];
    __half* s_lam = (__half*)dyn;                        // [8][H][R][HD]
    float*  s_v   = (float*)(dyn + 8*HH*RR*HD*2);        // [8][H][HD]
    __shared__ float s_cs[8][32];
    __shared__ float s_sn[8][32];
    __shared__ float s_alpha[8];
    __shared__ int   s_idx[8];

    int b = blockIdx.x >> 11, l = blockIdx.x & 2047;
    int tid = threadIdx.x;
    int wi = tid >> 5, ln = tid & 31;

    {
        const float4* src = (const float4*)(g_LamH + ((size_t)b * EE + (size_t)l * 8) * NLAM);
        float4* dst = (float4*)s_lam;
#pragma unroll
        for (int i = 0; i < 16; i++) dst[tid + i * 256] = src[tid + i * 256];
    }
    {
        int e = wi;
        int j = g_idx[((size_t)b * LL + l) * WWIN + e];
        if (ln == 0) {
            s_idx[e] = j;
            s_alpha[e] = g_alpha[(size_t)b * EE + l * WWIN + e];
        }
        float ang = (float)(l - j) * exp2f((float)ln * -0.41524101186092029f);
        s_cs[e][ln] = cosf(ang);
        s_sn[e][ln] = sinf(ang);
    }
    __syncthreads();
#pragma unroll
    for (int i = 0; i < 16; i++) {
        int gid = tid + i * 256;
        int e2 = gid >> 9, h2 = (gid >> 6) & 7, d = gid & 63;
        s_v[gid] = g_v[(((size_t)b * HH + h2) * KK + s_idx[e2]) * HD + d];
    }
    __syncthreads();

    size_t ubase = (((size_t)b * HH + wi) * LL + l) * HD;
    float u0 = g_u[ubase + ln];
    float u1 = g_u[ubase + 32 + ln];

#pragma unroll
    for (int t = 0; t < TT; t++) {
        float stp = softplusf(step_sizes[t * LL + l]);
        float acc0 = 0.f, acc1 = 0.f;
#pragma unroll
        for (int e = 0; e < WWIN; e++) {
            float cv = s_cs[e][ln], sv = s_sn[e][ln];
            float ui0 = u0 * cv - u1 * sv;
            float ui1 = u1 * cv + u0 * sv;
            float d0 = ui0 - s_v[(e * HH + wi) * HD + ln];
            float d1 = ui1 - s_v[(e * HH + wi) * HD + 32 + ln];
            float al = s_alpha[e];
            float r0 = al * d0, r1 = al * d1;
            const __half* lp = s_lam + ((e * HH + wi) * RR) * HD;
#pragma unroll
            for (int r = 0; r < RR; r++) {
                float l0 = __half2float(lp[r * HD + ln]);
                float l1 = __half2float(lp[r * HD + 32 + ln]);
                float p = l0 * d0 + l1 * d1;
#pragma unroll
                for (int o = 16; o; o >>= 1) p += __shfl_xor_sync(0xffffffffu, p, o);
                r0 += p * l0;
                r1 += p * l1;
            }
            acc0 += r0;
            acc1 += r1;
        }
        u0 -= stp * acc0;
        u1 -= stp * acc1;
    }
    g_u[ubase + ln]      = u0;
    g_u[ubase + 32 + ln] = u1;
}

// ---------------- launch ----------------
extern "C" void kernel_launch(void* const* d_in, const int* in_sizes, int n_in,
                              void* d_out, int out_size)
{
    const float* target = (const float*)d_in[0];
    const float* context= (const float*)d_in[1];
    const float* Wt  = (const float*)d_in[2];
    const float* bt  = (const float*)d_in[3];
    const float* Wc  = (const float*)d_in[4];
    const float* bc  = (const float*)d_in[5];
    const float* Ws1 = (const float*)d_in[6];
    const float* bs1 = (const float*)d_in[7];
    const float* Ws2 = (const float*)d_in[8];
    const float* bs2 = (const float*)d_in[9];
    const float* Wa1 = (const float*)d_in[10];
    const float* ba1 = (const float*)d_in[11];
    const float* Wa2 = (const float*)d_in[12];
    const float* ba2 = (const float*)d_in[13];
    const float* Wl1 = (const float*)d_in[14];
    const float* bl1 = (const float*)d_in[15];
    const float* Wl2 = (const float*)d_in[16];
    const float* bl2 = (const float*)d_in[17];
    const float* step_sizes = (const float*)d_in[18];
    const float* Wo  = (const float*)d_in[19];
    const float* bo  = (const float*)d_in[20];

    float *pu, *pv, *pSA, *pSB, *pAA, *pAB, *pLA, *pLB;
    cudaGetSymbolAddress((void**)&pu,  g_u);
    cudaGetSymbolAddress((void**)&pv,  g_v);
    cudaGetSymbolAddress((void**)&pSA, g_SA);
    cudaGetSymbolAddress((void**)&pSB, g_SB);
    cudaGetSymbolAddress((void**)&pAA, g_AA);
    cudaGetSymbolAddress((void**)&pAB, g_AB);
    cudaGetSymbolAddress((void**)&pLA, g_LA);
    cudaGetSymbolAddress((void**)&pLB, g_LB);

    cudaFuncSetAttribute(iter2_kernel, cudaFuncAttributeMaxDynamicSharedMemorySize,
                         ITER_DYN_SMEM);

    const int Mrows = BB * LL;  // 4096

    // u = target@Wt+bt ; v = context@Wc+bc  (stored [B,H,*,HD]) — tf32 tensor cores
    gemm32_kernel<<<dim3(DD/64, Mrows/128), 256>>>(target,  Wt, bt, pu, Mrows, DD, DD, 0, 1);
    gemm32_kernel<<<dim3(DD/64, Mrows/128), 256>>>(context, Wc, bc, pv, Mrows, DD, DD, 0, 1);

    // Wl2 -> [n][k] fp16
    prep_wl2_kernel<<<(NLAM + 255) / 256, 256>>>(Wl2);

    // separable 16-dim projections (both inputs in one launch, grid 256)
    proj_fused_kernel<<<256, 256>>>(target, context, Ws1, Wa1, Wl1,
                                    pSA, pAA, pLA, pSB, pAB, pLB);

    // scores + top-8
    score_topk_kernel<<<BB * LL, 256>>>(bs1, Ws2, bs2);

    // per-edge small params (gh fp16 + alpha)
    edge_small_kernel<<<(BB * EE * 32 + 255) / 256, 256>>>(bl1, ba1, Wa2, ba2);

    // Lam(fp16) = normalize_chunks( gh @ Wl2 + bl2 ) — f16 tensor cores, fused norm
    lam_mma_kernel<<<dim3(NLAM/64, (BB*EE)/128), 256>>>(bl2);

    // both consensus iterations fused
    iter2_kernel<<<BB * LL, 256, ITER_DYN_SMEM>>>(step_sizes);

    // y = u^T @ Wo + bo  (A gathered from u layout)
    gemm32_kernel<<<dim3(DD/64, Mrows/128), 256>>>(pu, Wo, bo, (float*)d_out,
                                                   Mrows, DD, DD, 1, 0);
}

// round 4
// speedup vs baseline: 1.8332x; 1.1462x over previous
#include <cuda_runtime.h>
#include <cuda_fp16.h>
#include <cstdint>

// Problem constants
#define BB 2
#define LL 2048
#define KK 2048
#define DD 512
#define HH 8
#define HD 64
#define RR 8
#define WWIN 8
#define EE (LL*WWIN)          // 16384 edges per batch
#define EH 16
#define TT 2
#define NLAM (HH*RR*HD)       // 4096
#define SCAP 224              // survivor cap in score kernel
#define LAMP 4112             // padded halves per edge chunk in iter2 smem (4096+16)

// ---------------- scratch (allocation-free: static device globals) ----------------
__device__ float  g_u [BB*HH*LL*HD];          // [B,H,L,HD]
__device__ float  g_v [BB*HH*KK*HD];          // [B,H,K,HD]
__device__ float  g_SA[BB*LL*EH];
__device__ float  g_SB[BB*KK*EH];
__device__ float  g_AA[BB*LL*EH];
__device__ float  g_AB[BB*KK*EH];
__device__ float  g_LA[BB*LL*EH];
__device__ float  g_LB[BB*KK*EH];
__device__ int    g_idx[BB*LL*WWIN];
__device__ __half g_gh[BB*EE*EH];             // gelu(h) per edge, fp16 (A of Lam mma)
__device__ float  g_alpha[BB*EE];
__device__ __half g_Wl2h[NLAM*EH];            // Wl2 transposed [n][k] fp16
__device__ __half g_LamH[(size_t)BB*EE*NLAM]; // 256MB

// ---------------- helpers ----------------
__device__ __forceinline__ float geluf(float x){
    return 0.5f * x * (1.0f + erff(x * 0.7071067811865475244f));
}
__device__ __forceinline__ float tanh_ap(float x){
    float r; asm("tanh.approx.f32 %0, %1;" : "=f"(r) : "f"(x)); return r;
}
__device__ __forceinline__ float gelu_approx(float x){
    float t = 0.7978845608f * x * (1.0f + 0.044715f * x * x);
    return 0.5f * x * (1.0f + tanh_ap(t));
}
__device__ __forceinline__ float softplusf(float x){
    return (x > 20.f) ? x : log1pf(expf(x));
}
__device__ __forceinline__ float tf32_rna(float x){
    uint32_t u;
    asm("cvt.rna.tf32.f32 %0, %1;" : "=r"(u) : "f"(x));
    return __uint_as_float(u);
}
__device__ __forceinline__ void mma_tf32(float* d, const uint32_t* a, const uint32_t* b){
    asm("mma.sync.aligned.m16n8k8.row.col.f32.tf32.tf32.f32 "
        "{%0,%1,%2,%3}, {%4,%5,%6,%7}, {%8,%9}, {%0,%1,%2,%3};"
        : "+f"(d[0]), "+f"(d[1]), "+f"(d[2]), "+f"(d[3])
        : "r"(a[0]), "r"(a[1]), "r"(a[2]), "r"(a[3]), "r"(b[0]), "r"(b[1]));
}
__device__ __forceinline__ void mma_f16(float* d, uint32_t a0, uint32_t a1, uint32_t a2,
                                        uint32_t a3, uint32_t b0, uint32_t b1){
    asm("mma.sync.aligned.m16n8k16.row.col.f32.f16.f16.f32 "
        "{%0,%1,%2,%3}, {%4,%5,%6,%7}, {%8,%9}, {%0,%1,%2,%3};"
        : "+f"(d[0]), "+f"(d[1]), "+f"(d[2]), "+f"(d[3])
        : "r"(a0), "r"(a1), "r"(a2), "r"(a3), "r"(b0), "r"(b1));
}

// ---------------- tf32 tensor-core GEMM: C = A[MxK] @ W[KxN] + bias ----------------
// aload: 0 = A row-major; 1 = A gathered from u layout [B,H,L,HD]
// smode: 0 = plain C[m*N+n]; 1 = store to u/v layout [B,H,*,HD]
// halfM != 0: blocks with bm >= halfM switch to (A2, W2, bias2, C2), bm -= halfM
__global__ __launch_bounds__(256) void gemm32_kernel(
    const float* A, const float* W, const float* bias, float* C,
    int M, int N, int Kd, int aload, int smode,
    const float* A2, const float* W2, const float* bias2, float* C2, int halfM)
{
    __shared__ float As[128][36];
    __shared__ float Bs[32][72];
    int bm = blockIdx.y * 128;
    const int bn = blockIdx.x * 64;
    if (halfM && bm >= halfM) { A = A2; W = W2; bias = bias2; C = C2; bm -= halfM; }
    const int tid  = threadIdx.x;
    const int warp = tid >> 5, lane = tid & 31;
    const int wm = warp & 3, wn = warp >> 2;
    const int q = lane >> 2, c = lane & 3;

    float d[2][4][4];
#pragma unroll
    for (int mt = 0; mt < 2; mt++)
#pragma unroll
        for (int nt = 0; nt < 4; nt++)
#pragma unroll
            for (int i = 0; i < 4; i++) d[mt][nt][i] = 0.f;

    for (int k0 = 0; k0 < Kd; k0 += 32) {
#pragma unroll
        for (int i = 0; i < 4; i++) {
            int id = tid + i * 256;
            int m = id >> 3, kq = (id & 7) * 4;
            float4 v;
            if (aload) {
                int mm = bm + m; int b = mm >> 11, l = mm & 2047;
                int k = k0 + kq; int h = k >> 6, hd = k & 63;
                v = *(const float4*)&A[(((size_t)b * HH + h) * LL + l) * HD + hd];
            } else {
                v = *(const float4*)&A[(size_t)(bm + m) * Kd + k0 + kq];
            }
            float4 t = make_float4(tf32_rna(v.x), tf32_rna(v.y), tf32_rna(v.z), tf32_rna(v.w));
            *(float4*)&As[m][kq] = t;
        }
#pragma unroll
        for (int i = 0; i < 2; i++) {
            int id = tid + i * 256;
            int kk = id >> 4, nq = (id & 15) * 4;
            float4 v = *(const float4*)&W[(size_t)(k0 + kk) * N + bn + nq];
            float4 t = make_float4(tf32_rna(v.x), tf32_rna(v.y), tf32_rna(v.z), tf32_rna(v.w));
            *(float4*)&Bs[kk][nq] = t;
        }
        __syncthreads();
#pragma unroll
        for (int k8 = 0; k8 < 4; k8++) {
            uint32_t a[2][4], b[4][2];
#pragma unroll
            for (int mt = 0; mt < 2; mt++) {
                int r0 = wm * 32 + mt * 16 + q;
                a[mt][0] = __float_as_uint(As[r0    ][k8 * 8 + c]);
                a[mt][1] = __float_as_uint(As[r0 + 8][k8 * 8 + c]);
                a[mt][2] = __float_as_uint(As[r0    ][k8 * 8 + c + 4]);
                a[mt][3] = __float_as_uint(As[r0 + 8][k8 * 8 + c + 4]);
            }
#pragma unroll
            for (int nt = 0; nt < 4; nt++) {
                int cn = wn * 32 + nt * 8 + q;
                b[nt][0] = __float_as_uint(Bs[k8 * 8 + c    ][cn]);
                b[nt][1] = __float_as_uint(Bs[k8 * 8 + c + 4][cn]);
            }
#pragma unroll
            for (int mt = 0; mt < 2; mt++)
#pragma unroll
                for (int nt = 0; nt < 4; nt++)
                    mma_tf32(d[mt][nt], a[mt], b[nt]);
        }
        __syncthreads();
    }

#pragma unroll
    for (int mt = 0; mt < 2; mt++) {
        int gm0 = bm + wm * 32 + mt * 16 + q;
#pragma unroll
        for (int nt = 0; nt < 4; nt++) {
            int gn = bn + wn * 32 + nt * 8 + 2 * c;
            float b0 = __ldg(&bias[gn]), b1 = __ldg(&bias[gn + 1]);
            float v0 = d[mt][nt][0] + b0, v1 = d[mt][nt][1] + b1;
            float v2 = d[mt][nt][2] + b0, v3 = d[mt][nt][3] + b1;
            if (smode == 1) {
                int bb = gm0 >> 11, l = gm0 & 2047, h = gn >> 6, hd = gn & 63;
                float* p0 = &C[(((size_t)bb * HH + h) * LL + l) * HD + hd];
                p0[0] = v0; p0[1] = v1;
                float* p2 = &C[(((size_t)bb * HH + h) * LL + (l + 8)) * HD + hd];
                p2[0] = v2; p2[1] = v3;
            } else {
                *(float2*)&C[(size_t)gm0 * N + gn] = make_float2(v0, v1);
                *(float2*)&C[(size_t)(gm0 + 8) * N + gn] = make_float2(v2, v3);
            }
        }
    }
}

// ---------------- Wl2 transpose+convert: [16][4096] f32 -> [4096][16] f16 ----------
__global__ void prep_wl2_kernel(const float* __restrict__ Wl2)
{
    int n = blockIdx.x * blockDim.x + threadIdx.x;
    if (n >= NLAM) return;
#pragma unroll
    for (int k = 0; k < EH; k++)
        g_Wl2h[n * EH + k] = __float2half(Wl2[(size_t)k * NLAM + n]);
}

// ---------------- Lam fp16 MMA + fused chunk-normalization ------------------------
__global__ __launch_bounds__(256) void lam_mma_kernel(const float* __restrict__ bl2)
{
    __shared__ __half Ws[64][24];
    __shared__ float  Wb[64];
    const int n0 = blockIdx.x * 64;
    const int m0 = blockIdx.y * 128;
    const int tid = threadIdx.x;
    const int warp = tid >> 5, lane = tid & 31;
    const int q = lane >> 2, c = lane & 3;

    if (tid < 128) {
        int nl = tid >> 1, part = tid & 1;
        *(int4*)&Ws[nl][part * 8] = *(const int4*)&g_Wl2h[(size_t)(n0 + nl) * EH + part * 8];
    }
    if (tid < 64) Wb[tid] = bl2[n0 + tid];
    __syncthreads();

    const int ra = m0 + warp * 16 + q;
    const uint32_t* ar0 = (const uint32_t*)&g_gh[(size_t)ra * EH];
    const uint32_t* ar1 = (const uint32_t*)&g_gh[(size_t)(ra + 8) * EH];
    uint32_t a0 = ar0[c], a1 = ar1[c], a2 = ar0[c + 4], a3 = ar1[c + 4];

    float d[8][4];
#pragma unroll
    for (int nt = 0; nt < 8; nt++) { d[nt][0]=d[nt][1]=d[nt][2]=d[nt][3]=0.f; }
#pragma unroll
    for (int nt = 0; nt < 8; nt++) {
        int nl = nt * 8 + q;
        uint32_t b0 = *(const uint32_t*)&Ws[nl][2 * c];
        uint32_t b1 = *(const uint32_t*)&Ws[nl][2 * c + 8];
        mma_f16(d[nt], a0, a1, a2, a3, b0, b1);
    }

    float s0 = 0.f, s1 = 0.f;
#pragma unroll
    for (int nt = 0; nt < 8; nt++) {
        float bA = Wb[nt * 8 + 2 * c], bB = Wb[nt * 8 + 2 * c + 1];
        d[nt][0] += bA; d[nt][1] += bB; d[nt][2] += bA; d[nt][3] += bB;
        s0 += d[nt][0] * d[nt][0] + d[nt][1] * d[nt][1];
        s1 += d[nt][2] * d[nt][2] + d[nt][3] * d[nt][3];
    }
    s0 += __shfl_xor_sync(0xffffffffu, s0, 1); s0 += __shfl_xor_sync(0xffffffffu, s0, 2);
    s1 += __shfl_xor_sync(0xffffffffu, s1, 1); s1 += __shfl_xor_sync(0xffffffffu, s1, 2);
    float sc0 = 1.f / fmaxf(sqrtf(s0), 1e-12f);
    float sc1 = 1.f / fmaxf(sqrtf(s1), 1e-12f);
#pragma unroll
    for (int nt = 0; nt < 8; nt++) {
        int col = n0 + nt * 8 + 2 * c;
        *(__half2*)&g_LamH[(size_t)ra * NLAM + col] =
            __floats2half2_rn(d[nt][0] * sc0, d[nt][1] * sc0);
        *(__half2*)&g_LamH[(size_t)(ra + 8) * NLAM + col] =
            __floats2half2_rn(d[nt][2] * sc1, d[nt][3] * sc1);
    }
}

// ---------------- 512->48 projection (both inputs), 12 cols/thread ----------------
__global__ __launch_bounds__(128) void proj_kernel(
    const float* __restrict__ Xt, const float* __restrict__ Xc,
    const float* __restrict__ W1, const float* __restrict__ W2, const float* __restrict__ W3,
    float* __restrict__ O1t, float* __restrict__ O2t, float* __restrict__ O3t,
    float* __restrict__ O1c, float* __restrict__ O2c, float* __restrict__ O3c)
{
    __shared__ float Xs[32][68];
    __shared__ float Ws[64][52];
    const int grow0 = blockIdx.x * 32;
    const int sel = grow0 >= (BB * LL);
    const float* X = sel ? Xc : Xt;
    const int row0 = grow0 & (BB * LL - 1);
    const int koff = sel ? DD : 0;
    const int tid = threadIdx.x;
    const int r = tid >> 2, c0 = (tid & 3) * 12;

    float acc[12];
#pragma unroll
    for (int j = 0; j < 12; j++) acc[j] = 0.f;

    for (int k0 = 0; k0 < DD; k0 += 64) {
#pragma unroll
        for (int i = 0; i < 4; i++) {
            int id = tid + i * 128;
            int rr = id >> 4, qq = (id & 15) * 4;
            *(float4*)&Xs[rr][qq] = *(const float4*)&X[(size_t)(row0 + rr) * DD + k0 + qq];
        }
#pragma unroll
        for (int i = 0; i < 2; i++) {
            int id = tid + i * 128;
            int kr = id >> 2, qq = (id & 3) * 4;
            *(float4*)&Ws[kr][ 0 + qq] = *(const float4*)&W1[(size_t)(koff + k0 + kr) * EH + qq];
            *(float4*)&Ws[kr][16 + qq] = *(const float4*)&W2[(size_t)(koff + k0 + kr) * EH + qq];
            *(float4*)&Ws[kr][32 + qq] = *(const float4*)&W3[(size_t)(koff + k0 + kr) * EH + qq];
        }
        __syncthreads();
#pragma unroll
        for (int k = 0; k < 64; k++) {
            float x = Xs[r][k];
            float4 w0 = *(const float4*)&Ws[k][c0];
            float4 w1 = *(const float4*)&Ws[k][c0 + 4];
            float4 w2 = *(const float4*)&Ws[k][c0 + 8];
            acc[0] += x * w0.x;  acc[1] += x * w0.y;  acc[2]  += x * w0.z;  acc[3]  += x * w0.w;
            acc[4] += x * w1.x;  acc[5] += x * w1.y;  acc[6]  += x * w1.z;  acc[7]  += x * w1.w;
            acc[8] += x * w2.x;  acc[9] += x * w2.y;  acc[10] += x * w2.z;  acc[11] += x * w2.w;
        }
        __syncthreads();
    }

    const int row = row0 + r;
#pragma unroll
    for (int j = 0; j < 12; j++) {
        int cc = c0 + j;
        int m = cc >> 4, col = cc & 15;
        float* O = sel ? (m == 0 ? O1c : m == 1 ? O2c : O3c)
                       : (m == 0 ? O1t : m == 1 ? O2t : O3t);
        O[(size_t)row * EH + col] = acc[j];
    }
}

// ---------------- score + top-8: approx prune + exact rescue ----------------
__global__ __launch_bounds__(256) void score_topk_kernel(
    const float* __restrict__ bs1, const float* __restrict__ Ws2, const float* __restrict__ bs2)
{
    __shared__ float sc[KK];
    __shared__ float a16[EH];
    __shared__ float w2s[EH];
    __shared__ unsigned long long wred[8];
    __shared__ unsigned long long s_keys[256];
    __shared__ int s_surv[SCAP];
    __shared__ int s_sel[8];
    __shared__ int s_cnt, s_win;
    __shared__ float s_thr, s_lastv;

    int b = blockIdx.x >> 11, l = blockIdx.x & 2047;
    int tid = threadIdx.x;
    int warp = tid >> 5, lane = tid & 31;
    if (tid < EH) {
        a16[tid] = g_SA[((size_t)b * LL + l) * EH + tid] + bs1[tid];
        w2s[tid] = Ws2[tid];
    }
    __syncthreads();
    float aR[EH], wR[EH];
#pragma unroll
    for (int c = 0; c < EH; c++) { aR[c] = a16[c]; wR[c] = w2s[c]; }
    float bs2v = bs2[0];

    // phase A: approx scores (HW tanh gelu)
    for (int i = 0; i < KK / 256; i++) {
        int kk = tid + i * 256;
        const float4* bp = (const float4*)(g_SB + ((size_t)b * KK + kk) * EH);
        float4 b0 = bp[0], b1 = bp[1], b2 = bp[2], b3 = bp[3];
        float bv[EH] = {b0.x,b0.y,b0.z,b0.w, b1.x,b1.y,b1.z,b1.w,
                        b2.x,b2.y,b2.z,b2.w, b3.x,b3.y,b3.z,b3.w};
        float s = bs2v;
#pragma unroll
        for (int c = 0; c < EH; c++) s += gelu_approx(aR[c] + bv[c]) * wR[c];
        sc[kk] = s;
    }
    __syncthreads();

    // approx top-8 (tracks 8th value, no g_idx writes)
    for (int w = 0; w < WWIN; w++) {
        unsigned long long best = 0ull;
#pragma unroll
        for (int i = 0; i < KK / 256; i++) {
            int kk = tid + i * 256;
            unsigned u = __float_as_uint(sc[kk]);
            u = (u & 0x80000000u) ? ~u : (u | 0x80000000u);
            unsigned long long key = (((unsigned long long)u) << 32) | (unsigned)(KK - 1 - kk);
            if (key > best) best = key;
        }
#pragma unroll
        for (int o = 16; o; o >>= 1) {
            unsigned long long other = __shfl_xor_sync(0xffffffffu, best, o);
            if (other > best) best = other;
        }
        if (lane == 0) wred[warp] = best;
        __syncthreads();
        if (tid == 0) {
            unsigned long long top = wred[0];
#pragma unroll
            for (int i = 1; i < 8; i++) if (wred[i] > top) top = wred[i];
            int idx = KK - 1 - (int)(top & 0xffffffffu);
            s_sel[w] = idx;
            s_lastv = sc[idx];
            sc[idx] = __int_as_float(0xff800000);
        }
        __syncthreads();
    }

    // threshold from provable approx-error bound: B = sum|w| * 0.01 + 1e-3
    if (tid == 0) {
        float sw = 0.f;
#pragma unroll
        for (int c = 0; c < EH; c++) sw += fabsf(w2s[c]);
        s_thr = s_lastv - (sw * 0.02f + 2e-3f);   // t8 - 2B
        s_cnt = 8;
    }
    __syncthreads();
    if (tid < 8) s_surv[tid] = s_sel[tid];
    for (int i = 0; i < KK / 256; i++) {
        int kk = tid + i * 256;
        if (sc[kk] >= s_thr) {
            int p = atomicAdd(&s_cnt, 1);
            if (p < SCAP) s_surv[p] = kk;
        }
    }
    __syncthreads();
    int n = s_cnt;

    if (n <= SCAP) {
        // exact rescore of survivors only
        unsigned long long key = 0ull;
        if (tid < n) {
            int kk = s_surv[tid];
            const float4* bp = (const float4*)(g_SB + ((size_t)b * KK + kk) * EH);
            float4 b0 = bp[0], b1 = bp[1], b2 = bp[2], b3 = bp[3];
            float bv[EH] = {b0.x,b0.y,b0.z,b0.w, b1.x,b1.y,b1.z,b1.w,
                            b2.x,b2.y,b2.z,b2.w, b3.x,b3.y,b3.z,b3.w};
            float s = bs2v;
#pragma unroll
            for (int c = 0; c < EH; c++) s += geluf(aR[c] + bv[c]) * wR[c];
            unsigned u = __float_as_uint(s);
            u = (u & 0x80000000u) ? ~u : (u | 0x80000000u);
            key = (((unsigned long long)u) << 32) | (unsigned)(KK - 1 - kk);
        }
        s_keys[tid] = key;
        __syncthreads();
        for (int w = 0; w < WWIN; w++) {
            unsigned long long best = s_keys[tid];
#pragma unroll
            for (int o = 16; o; o >>= 1) {
                unsigned long long other = __shfl_xor_sync(0xffffffffu, best, o);
                if (other > best) best = other;
            }
            if (lane == 0) wred[warp] = best;
            __syncthreads();
            if (tid == 0) {
                unsigned long long top = wred[0];
#pragma unroll
                for (int i = 1; i < 8; i++) if (wred[i] > top) top = wred[i];
                int idx = KK - 1 - (int)(top & 0xffffffffu);
                g_idx[((size_t)b * LL + l) * WWIN + w] = idx;
                s_win = idx;
            }
            __syncthreads();
            if (tid < n && s_surv[tid] == s_win) s_keys[tid] = 0ull;
            __syncthreads();
        }
    } else {
        // fallback: exact for all candidates (pathological near-tie storm)
        for (int i = 0; i < KK / 256; i++) {
            int kk = tid + i * 256;
            const float4* bp = (const float4*)(g_SB + ((size_t)b * KK + kk) * EH);
            float4 b0 = bp[0], b1 = bp[1], b2 = bp[2], b3 = bp[3];
            float bv[EH] = {b0.x,b0.y,b0.z,b0.w, b1.x,b1.y,b1.z,b1.w,
                            b2.x,b2.y,b2.z,b2.w, b3.x,b3.y,b3.z,b3.w};
            float s = bs2v;
#pragma unroll
            for (int c = 0; c < EH; c++) s += geluf(aR[c] + bv[c]) * wR[c];
            sc[kk] = s;
        }
        __syncthreads();
        for (int w = 0; w < WWIN; w++) {
            unsigned long long best = 0ull;
#pragma unroll
            for (int i = 0; i < KK / 256; i++) {
                int kk = tid + i * 256;
                unsigned u = __float_as_uint(sc[kk]);
                u = (u & 0x80000000u) ? ~u : (u | 0x80000000u);
                unsigned long long key = (((unsigned long long)u) << 32) | (unsigned)(KK - 1 - kk);
                if (key > best) best = key;
            }
#pragma unroll
            for (int o = 16; o; o >>= 1) {
                unsigned long long other = __shfl_xor_sync(0xffffffffu, best, o);
                if (other > best) best = other;
            }
            if (lane == 0) wred[warp] = best;
            __syncthreads();
            if (tid == 0) {
                unsigned long long top = wred[0];
#pragma unroll
                for (int i = 1; i < 8; i++) if (wred[i] > top) top = wred[i];
                int idx = KK - 1 - (int)(top & 0xffffffffu);
                g_idx[((size_t)b * LL + l) * WWIN + w] = idx;
                sc[idx] = __int_as_float(0xff800000);
            }
            __syncthreads();
        }
    }
}

// ---------------- per-edge small params: gh (fp16), alpha ----------------
__global__ void edge_small_kernel(const float* __restrict__ bl1, const float* __restrict__ ba1,
                                  const float* __restrict__ Wa2, const float* __restrict__ ba2)
{
    int gw = (blockIdx.x * blockDim.x + threadIdx.x) >> 5;
    int ln = threadIdx.x & 31;
    if (gw >= BB * EE) return;
    int b = gw >> 14, e = gw & (EE - 1);
    int l = e >> 3, w = e & 7;
    int j = g_idx[((size_t)b * LL + l) * WWIN + w];
    int i = l;

    float hav = 0.f;
    if (ln < EH) {
        int c = ln;
        float hl = g_LA[((size_t)b * LL + i) * EH + c] + g_LB[((size_t)b * KK + j) * EH + c] + bl1[c];
        g_gh[(size_t)gw * EH + c] = __float2half(geluf(hl));
        float ha = g_AA[((size_t)b * LL + i) * EH + c] + g_AB[((size_t)b * KK + j) * EH + c] + ba1[c];
        hav = geluf(ha) * Wa2[c];
    }
#pragma unroll
    for (int o = 16; o; o >>= 1) hav += __shfl_xor_sync(0xffffffffu, hav, o);
    if (ln == 0) g_alpha[gw] = softplusf(hav + ba2[0]);
}

// ---------------- fused T=2 consensus: warp=head, 4 edges concurrent per warp -----
// Lane = (eg, dg): eg = edge-in-quad (4), dg = d-octet (8). Lane owns 8 d's:
// d = dg*4+i (lo) and d+32 (hi). Dot reduce over 8 lanes (3 shfl), cross-eg
// combine at iteration end (2 shfl per value). Lam smem padded 16 halves/edge.
#define ITER_DYN_SMEM (8*LAMP*2 + 8*HH*HD*4)   // 65792 + 16384 = 82176 B
__global__ __launch_bounds__(256) void iter2_kernel(const float* __restrict__ step_sizes)
{
    extern __shared__ char dyn[];
    __half* s_lam = (__half*)dyn;                        // [8e] x LAMP halves
    float*  s_v   = (float*)(dyn + 8*LAMP*2);            // [8e][H][64]
    __shared__ float s_cs[8][32];
    __shared__ float s_sn[8][32];
    __shared__ float s_alpha[8];
    __shared__ int   s_idx[8];

    int b = blockIdx.x >> 11, l = blockIdx.x & 2047;
    int tid = threadIdx.x;
    int wi = tid >> 5, ln = tid & 31;
    int eg = ln >> 3, dg = ln & 7;

    // stage Lam with 2-float4 (16-half) pad per edge chunk
    {
        const float4* src = (const float4*)(g_LamH + ((size_t)b * EE + (size_t)l * 8) * NLAM);
        float4* dst = (float4*)s_lam;
#pragma unroll
        for (int i = 0; i < 16; i++) {
            int s = tid + i * 256;
            dst[s + (s >> 9) * 2] = src[s];
        }
    }
    {
        int e = wi;
        int j = g_idx[((size_t)b * LL + l) * WWIN + e];
        if (ln == 0) { s_idx[e] = j; s_alpha[e] = g_alpha[(size_t)b * EE + l * WWIN + e]; }
        float ang = (float)(l - j) * exp2f((float)ln * -0.41524101186092029f);
        s_cs[e][ln] = cosf(ang);
        s_sn[e][ln] = sinf(ang);
    }
    __syncthreads();
#pragma unroll
    for (int i = 0; i < 16; i++) {
        int gid = tid + i * 256;
        int e2 = gid >> 9, h2 = (gid >> 6) & 7, d = gid & 63;
        s_v[gid] = g_v[(((size_t)b * HH + h2) * KK + s_idx[e2]) * HD + d];
    }
    __syncthreads();

    size_t ubase = (((size_t)b * HH + wi) * LL + l) * HD;
    float4 u_lo = *(const float4*)&g_u[ubase + dg * 4];
    float4 u_hi = *(const float4*)&g_u[ubase + 32 + dg * 4];

#pragma unroll
    for (int t = 0; t < TT; t++) {
        float stp = softplusf(step_sizes[t * LL + l]);
        float al4[4] = {0.f,0.f,0.f,0.f}, ah4[4] = {0.f,0.f,0.f,0.f};
#pragma unroll
        for (int eb = 0; eb < 2; eb++) {
            int e = eb * 4 + eg;
            float4 cs4 = *(const float4*)&s_cs[e][dg * 4];
            float4 sn4 = *(const float4*)&s_sn[e][dg * 4];
            const float4* vp = (const float4*)&s_v[(e * HH + wi) * HD + dg * 4];
            float4 vlo = vp[0], vhi = vp[8];
            float dlo[4], dhi[4];
            dlo[0] = u_lo.x * cs4.x - u_hi.x * sn4.x - vlo.x;
            dlo[1] = u_lo.y * cs4.y - u_hi.y * sn4.y - vlo.y;
            dlo[2] = u_lo.z * cs4.z - u_hi.z * sn4.z - vlo.z;
            dlo[3] = u_lo.w * cs4.w - u_hi.w * sn4.w - vlo.w;
            dhi[0] = u_hi.x * cs4.x + u_lo.x * sn4.x - vhi.x;
            dhi[1] = u_hi.y * cs4.y + u_lo.y * sn4.y - vhi.y;
            dhi[2] = u_hi.z * cs4.z + u_lo.z * sn4.z - vhi.z;
            dhi[3] = u_hi.w * cs4.w + u_lo.w * sn4.w - vhi.w;
            float alp = s_alpha[e];
            float rl[4] = {0.f,0.f,0.f,0.f}, rh[4] = {0.f,0.f,0.f,0.f};
            const __half2* lp = (const __half2*)(s_lam + (size_t)e * LAMP + wi * RR * HD);
#pragma unroll
            for (int r = 0; r < RR; r++) {
                __half2 hl0 = lp[r * 32 + dg * 2], hl1 = lp[r * 32 + dg * 2 + 1];
                __half2 hh0 = lp[r * 32 + 16 + dg * 2], hh1 = lp[r * 32 + 16 + dg * 2 + 1];
                float2 f0 = __half22float2(hl0), f1 = __half22float2(hl1);
                float2 f2 = __half22float2(hh0), f3 = __half22float2(hh1);
                float p = f0.x * dlo[0] + f0.y * dlo[1] + f1.x * dlo[2] + f1.y * dlo[3]
                        + f2.x * dhi[0] + f2.y * dhi[1] + f3.x * dhi[2] + f3.y * dhi[3];
                p += __shfl_xor_sync(0xffffffffu, p, 1);
                p += __shfl_xor_sync(0xffffffffu, p, 2);
                p += __shfl_xor_sync(0xffffffffu, p, 4);
                rl[0] += p * f0.x; rl[1] += p * f0.y; rl[2] += p * f1.x; rl[3] += p * f1.y;
                rh[0] += p * f2.x; rh[1] += p * f2.y; rh[2] += p * f3.x; rh[3] += p * f3.y;
            }
#pragma unroll
            for (int i = 0; i < 4; i++) {
                al4[i] += alp * dlo[i] + rl[i];
                ah4[i] += alp * dhi[i] + rh[i];
            }
        }
        // combine the 4 edge-groups (lanes differing in bits 3,4)
#pragma unroll
        for (int i = 0; i < 4; i++) {
            al4[i] += __shfl_xor_sync(0xffffffffu, al4[i], 8);
            al4[i] += __shfl_xor_sync(0xffffffffu, al4[i], 16);
            ah4[i] += __shfl_xor_sync(0xffffffffu, ah4[i], 8);
            ah4[i] += __shfl_xor_sync(0xffffffffu, ah4[i], 16);
        }
        u_lo.x -= stp * al4[0]; u_lo.y -= stp * al4[1];
        u_lo.z -= stp * al4[2]; u_lo.w -= stp * al4[3];
        u_hi.x -= stp * ah4[0]; u_hi.y -= stp * ah4[1];
        u_hi.z -= stp * ah4[2]; u_hi.w -= stp * ah4[3];
    }
    if (eg == 0) {
        *(float4*)&g_u[ubase + dg * 4] = u_lo;
        *(float4*)&g_u[ubase + 32 + dg * 4] = u_hi;
    }
}

// ---------------- launch ----------------
extern "C" void kernel_launch(void* const* d_in, const int* in_sizes, int n_in,
                              void* d_out, int out_size)
{
    const float* target = (const float*)d_in[0];
    const float* context= (const float*)d_in[1];
    const float* Wt  = (const float*)d_in[2];
    const float* bt  = (const float*)d_in[3];
    const float* Wc  = (const float*)d_in[4];
    const float* bc  = (const float*)d_in[5];
    const float* Ws1 = (const float*)d_in[6];
    const float* bs1 = (const float*)d_in[7];
    const float* Ws2 = (const float*)d_in[8];
    const float* bs2 = (const float*)d_in[9];
    const float* Wa1 = (const float*)d_in[10];
    const float* ba1 = (const float*)d_in[11];
    const float* Wa2 = (const float*)d_in[12];
    const float* ba2 = (const float*)d_in[13];
    const float* Wl1 = (const float*)d_in[14];
    const float* bl1 = (const float*)d_in[15];
    const float* Wl2 = (const float*)d_in[16];
    const float* bl2 = (const float*)d_in[17];
    const float* step_sizes = (const float*)d_in[18];
    const float* Wo  = (const float*)d_in[19];
    const float* bo  = (const float*)d_in[20];

    float *pu, *pv, *pSA, *pSB, *pAA, *pAB, *pLA, *pLB;
    cudaGetSymbolAddress((void**)&pu,  g_u);
    cudaGetSymbolAddress((void**)&pv,  g_v);
    cudaGetSymbolAddress((void**)&pSA, g_SA);
    cudaGetSymbolAddress((void**)&pSB, g_SB);
    cudaGetSymbolAddress((void**)&pAA, g_AA);
    cudaGetSymbolAddress((void**)&pAB, g_AB);
    cudaGetSymbolAddress((void**)&pLA, g_LA);
    cudaGetSymbolAddress((void**)&pLB, g_LB);

    cudaFuncSetAttribute(iter2_kernel, cudaFuncAttributeMaxDynamicSharedMemorySize,
                         ITER_DYN_SMEM);

    const int Mrows = BB * LL;  // 4096

    // u and v projections in one launch (M = 8192, second half uses Wc/bc -> v)
    gemm32_kernel<<<dim3(DD/64, (2*Mrows)/128), 256>>>(
        target, Wt, bt, pu, 2*Mrows, DD, DD, 0, 1, context, Wc, bc, pv, Mrows);

    prep_wl2_kernel<<<(NLAM + 255) / 256, 256>>>(Wl2);

    // separable 16-dim projections (exact fp32 — feeds top-k)
    proj_kernel<<<(2*Mrows)/32, 128>>>(target, context, Ws1, Wa1, Wl1,
                                       pSA, pAA, pLA, pSB, pAB, pLB);

    // scores + top-8 (approx prune, exact rescue)
    score_topk_kernel<<<BB * LL, 256>>>(bs1, Ws2, bs2);

    edge_small_kernel<<<(BB * EE * 32 + 255) / 256, 256>>>(bl1, ba1, Wa2, ba2);

    lam_mma_kernel<<<dim3(NLAM/64, (BB*EE)/128), 256>>>(bl2);

    iter2_kernel<<<BB * LL, 256, ITER_DYN_SMEM>>>(step_sizes);

    gemm32_kernel<<<dim3(DD/64, Mrows/128), 256>>>(
        pu, Wo, bo, (float*)d_out, Mrows, DD, DD, 1, 0,
        nullptr, nullptr, nullptr, nullptr, 0);
}

// round 5
// speedup vs baseline: 1.8552x; 1.0120x over previous
#include <cuda_runtime.h>
#include <cuda_fp16.h>
#include <cstdint>

// Problem constants
#define BB 2
#define LL 2048
#define KK 2048
#define DD 512
#define HH 8
#define HD 64
#define RR 8
#define WWIN 8
#define EE (LL*WWIN)          // 16384 edges per batch
#define EH 16
#define TT 2
#define NLAM (HH*RR*HD)       // 4096
#define SCAP 224              // survivor cap in score kernel
#define LAMP 4112             // padded halves per edge chunk in iter2 smem (4096+16)

// ---------------- scratch (allocation-free: static device globals) ----------------
__device__ float  g_u [BB*HH*LL*HD];          // [B,H,L,HD]
__device__ float  g_v [BB*HH*KK*HD];          // [B,H,K,HD]
__device__ float  g_SA[BB*LL*EH];
__device__ float  g_SB[BB*KK*EH];
__device__ float  g_AA[BB*LL*EH];
__device__ float  g_AB[BB*KK*EH];
__device__ float  g_LA[BB*LL*EH];
__device__ float  g_LB[BB*KK*EH];
__device__ int    g_idx[BB*LL*WWIN];
__device__ __half g_gh[BB*EE*EH];             // gelu(h) per edge, fp16 (A of Lam mma)
__device__ float  g_alpha[BB*EE];
__device__ __half g_Wl2h[NLAM*EH];            // Wl2 transposed [n][k] fp16
__device__ __half g_LamH[(size_t)BB*EE*NLAM]; // 256MB

// ---------------- helpers ----------------
__device__ __forceinline__ float geluf(float x){
    return 0.5f * x * (1.0f + erff(x * 0.7071067811865475244f));
}
__device__ __forceinline__ float tanh_ap(float x){
    float r; asm("tanh.approx.f32 %0, %1;" : "=f"(r) : "f"(x)); return r;
}
__device__ __forceinline__ float gelu_approx(float x){
    float t = 0.7978845608f * x * (1.0f + 0.044715f * x * x);
    return 0.5f * x * (1.0f + tanh_ap(t));
}
__device__ __forceinline__ float softplusf(float x){
    return (x > 20.f) ? x : log1pf(expf(x));
}
__device__ __forceinline__ float tf32_rna(float x){
    uint32_t u;
    asm("cvt.rna.tf32.f32 %0, %1;" : "=r"(u) : "f"(x));
    return __uint_as_float(u);
}
__device__ __forceinline__ unsigned flipf(float s){
    unsigned u = __float_as_uint(s);
    return (u & 0x80000000u) ? ~u : (u | 0x80000000u);
}
__device__ __forceinline__ void mma_tf32(float* d, const uint32_t* a, const uint32_t* b){
    asm("mma.sync.aligned.m16n8k8.row.col.f32.tf32.tf32.f32 "
        "{%0,%1,%2,%3}, {%4,%5,%6,%7}, {%8,%9}, {%0,%1,%2,%3};"
        : "+f"(d[0]), "+f"(d[1]), "+f"(d[2]), "+f"(d[3])
        : "r"(a[0]), "r"(a[1]), "r"(a[2]), "r"(a[3]), "r"(b[0]), "r"(b[1]));
}
__device__ __forceinline__ void mma_f16(float* d, uint32_t a0, uint32_t a1, uint32_t a2,
                                        uint32_t a3, uint32_t b0, uint32_t b1){
    asm("mma.sync.aligned.m16n8k16.row.col.f32.f16.f16.f32 "
        "{%0,%1,%2,%3}, {%4,%5,%6,%7}, {%8,%9}, {%0,%1,%2,%3};"
        : "+f"(d[0]), "+f"(d[1]), "+f"(d[2]), "+f"(d[3])
        : "r"(a0), "r"(a1), "r"(a2), "r"(a3), "r"(b0), "r"(b1));
}
__device__ __forceinline__ unsigned long long warp_max_ull(unsigned long long v){
#pragma unroll
    for (int o = 16; o; o >>= 1) {
        unsigned long long w = __shfl_xor_sync(0xffffffffu, v, o);
        if (w > v) v = w;
    }
    return v;
}

// ---------------- tf32 tensor-core GEMM: C = A[MxK] @ W[KxN] + bias ----------------
// aload: 0 = A row-major; 1 = A gathered from u layout [B,H,L,HD]
// smode: 0 = plain C[m*N+n]; 1 = store to u/v layout [B,H,*,HD]
// halfM != 0: blocks with bm >= halfM switch to (A2, W2, bias2, C2), bm -= halfM
__global__ __launch_bounds__(256) void gemm32_kernel(
    const float* A, const float* W, const float* bias, float* C,
    int M, int N, int Kd, int aload, int smode,
    const float* A2, const float* W2, const float* bias2, float* C2, int halfM)
{
    __shared__ float As[128][36];
    __shared__ float Bs[32][72];
    int bm = blockIdx.y * 128;
    const int bn = blockIdx.x * 64;
    if (halfM && bm >= halfM) { A = A2; W = W2; bias = bias2; C = C2; bm -= halfM; }
    const int tid  = threadIdx.x;
    const int warp = tid >> 5, lane = tid & 31;
    const int wm = warp & 3, wn = warp >> 2;
    const int q = lane >> 2, c = lane & 3;

    float d[2][4][4];
#pragma unroll
    for (int mt = 0; mt < 2; mt++)
#pragma unroll
        for (int nt = 0; nt < 4; nt++)
#pragma unroll
            for (int i = 0; i < 4; i++) d[mt][nt][i] = 0.f;

    for (int k0 = 0; k0 < Kd; k0 += 32) {
#pragma unroll
        for (int i = 0; i < 4; i++) {
            int id = tid + i * 256;
            int m = id >> 3, kq = (id & 7) * 4;
            float4 v;
            if (aload) {
                int mm = bm + m; int b = mm >> 11, l = mm & 2047;
                int k = k0 + kq; int h = k >> 6, hd = k & 63;
                v = *(const float4*)&A[(((size_t)b * HH + h) * LL + l) * HD + hd];
            } else {
                v = *(const float4*)&A[(size_t)(bm + m) * Kd + k0 + kq];
            }
            float4 t = make_float4(tf32_rna(v.x), tf32_rna(v.y), tf32_rna(v.z), tf32_rna(v.w));
            *(float4*)&As[m][kq] = t;
        }
#pragma unroll
        for (int i = 0; i < 2; i++) {
            int id = tid + i * 256;
            int kk = id >> 4, nq = (id & 15) * 4;
            float4 v = *(const float4*)&W[(size_t)(k0 + kk) * N + bn + nq];
            float4 t = make_float4(tf32_rna(v.x), tf32_rna(v.y), tf32_rna(v.z), tf32_rna(v.w));
            *(float4*)&Bs[kk][nq] = t;
        }
        __syncthreads();
#pragma unroll
        for (int k8 = 0; k8 < 4; k8++) {
            uint32_t a[2][4], b[4][2];
#pragma unroll
            for (int mt = 0; mt < 2; mt++) {
                int r0 = wm * 32 + mt * 16 + q;
                a[mt][0] = __float_as_uint(As[r0    ][k8 * 8 + c]);
                a[mt][1] = __float_as_uint(As[r0 + 8][k8 * 8 + c]);
                a[mt][2] = __float_as_uint(As[r0    ][k8 * 8 + c + 4]);
                a[mt][3] = __float_as_uint(As[r0 + 8][k8 * 8 + c + 4]);
            }
#pragma unroll
            for (int nt = 0; nt < 4; nt++) {
                int cn = wn * 32 + nt * 8 + q;
                b[nt][0] = __float_as_uint(Bs[k8 * 8 + c    ][cn]);
                b[nt][1] = __float_as_uint(Bs[k8 * 8 + c + 4][cn]);
            }
#pragma unroll
            for (int mt = 0; mt < 2; mt++)
#pragma unroll
                for (int nt = 0; nt < 4; nt++)
                    mma_tf32(d[mt][nt], a[mt], b[nt]);
        }
        __syncthreads();
    }

#pragma unroll
    for (int mt = 0; mt < 2; mt++) {
        int gm0 = bm + wm * 32 + mt * 16 + q;
#pragma unroll
        for (int nt = 0; nt < 4; nt++) {
            int gn = bn + wn * 32 + nt * 8 + 2 * c;
            float b0 = __ldg(&bias[gn]), b1 = __ldg(&bias[gn + 1]);
            float v0 = d[mt][nt][0] + b0, v1 = d[mt][nt][1] + b1;
            float v2 = d[mt][nt][2] + b0, v3 = d[mt][nt][3] + b1;
            if (smode == 1) {
                int bb = gm0 >> 11, l = gm0 & 2047, h = gn >> 6, hd = gn & 63;
                float* p0 = &C[(((size_t)bb * HH + h) * LL + l) * HD + hd];
                p0[0] = v0; p0[1] = v1;
                float* p2 = &C[(((size_t)bb * HH + h) * LL + (l + 8)) * HD + hd];
                p2[0] = v2; p2[1] = v3;
            } else {
                *(float2*)&C[(size_t)gm0 * N + gn] = make_float2(v0, v1);
                *(float2*)&C[(size_t)(gm0 + 8) * N + gn] = make_float2(v2, v3);
            }
        }
    }
}

// ---------------- Wl2 transpose+convert: [16][4096] f32 -> [4096][16] f16 ----------
__global__ void prep_wl2_kernel(const float* __restrict__ Wl2)
{
    int n = blockIdx.x * blockDim.x + threadIdx.x;
    if (n >= NLAM) return;
#pragma unroll
    for (int k = 0; k < EH; k++)
        g_Wl2h[n * EH + k] = __float2half(Wl2[(size_t)k * NLAM + n]);
}

// ---------------- Lam fp16 MMA + fused chunk-normalization ------------------------
__global__ __launch_bounds__(256) void lam_mma_kernel(const float* __restrict__ bl2)
{
    __shared__ __half Ws[64][24];
    __shared__ float  Wb[64];
    const int n0 = blockIdx.x * 64;
    const int m0 = blockIdx.y * 128;
    const int tid = threadIdx.x;
    const int warp = tid >> 5, lane = tid & 31;
    const int q = lane >> 2, c = lane & 3;

    if (tid < 128) {
        int nl = tid >> 1, part = tid & 1;
        *(int4*)&Ws[nl][part * 8] = *(const int4*)&g_Wl2h[(size_t)(n0 + nl) * EH + part * 8];
    }
    if (tid < 64) Wb[tid] = bl2[n0 + tid];
    __syncthreads();

    const int ra = m0 + warp * 16 + q;
    const uint32_t* ar0 = (const uint32_t*)&g_gh[(size_t)ra * EH];
    const uint32_t* ar1 = (const uint32_t*)&g_gh[(size_t)(ra + 8) * EH];
    uint32_t a0 = ar0[c], a1 = ar1[c], a2 = ar0[c + 4], a3 = ar1[c + 4];

    float d[8][4];
#pragma unroll
    for (int nt = 0; nt < 8; nt++) { d[nt][0]=d[nt][1]=d[nt][2]=d[nt][3]=0.f; }
#pragma unroll
    for (int nt = 0; nt < 8; nt++) {
        int nl = nt * 8 + q;
        uint32_t b0 = *(const uint32_t*)&Ws[nl][2 * c];
        uint32_t b1 = *(const uint32_t*)&Ws[nl][2 * c + 8];
        mma_f16(d[nt], a0, a1, a2, a3, b0, b1);
    }

    float s0 = 0.f, s1 = 0.f;
#pragma unroll
    for (int nt = 0; nt < 8; nt++) {
        float bA = Wb[nt * 8 + 2 * c], bB = Wb[nt * 8 + 2 * c + 1];
        d[nt][0] += bA; d[nt][1] += bB; d[nt][2] += bA; d[nt][3] += bB;
        s0 += d[nt][0] * d[nt][0] + d[nt][1] * d[nt][1];
        s1 += d[nt][2] * d[nt][2] + d[nt][3] * d[nt][3];
    }
    s0 += __shfl_xor_sync(0xffffffffu, s0, 1); s0 += __shfl_xor_sync(0xffffffffu, s0, 2);
    s1 += __shfl_xor_sync(0xffffffffu, s1, 1); s1 += __shfl_xor_sync(0xffffffffu, s1, 2);
    float sc0 = 1.f / fmaxf(sqrtf(s0), 1e-12f);
    float sc1 = 1.f / fmaxf(sqrtf(s1), 1e-12f);
#pragma unroll
    for (int nt = 0; nt < 8; nt++) {
        int col = n0 + nt * 8 + 2 * c;
        *(__half2*)&g_LamH[(size_t)ra * NLAM + col] =
            __floats2half2_rn(d[nt][0] * sc0, d[nt][1] * sc0);
        *(__half2*)&g_LamH[(size_t)(ra + 8) * NLAM + col] =
            __floats2half2_rn(d[nt][2] * sc1, d[nt][3] * sc1);
    }
}

// ---------------- 512->48 projection (both inputs), 12 cols/thread ----------------
__global__ __launch_bounds__(128) void proj_kernel(
    const float* __restrict__ Xt, const float* __restrict__ Xc,
    const float* __restrict__ W1, const float* __restrict__ W2, const float* __restrict__ W3,
    float* __restrict__ O1t, float* __restrict__ O2t, float* __restrict__ O3t,
    float* __restrict__ O1c, float* __restrict__ O2c, float* __restrict__ O3c)
{
    __shared__ float Xs[32][68];
    __shared__ float Ws[64][52];
    const int grow0 = blockIdx.x * 32;
    const int sel = grow0 >= (BB * LL);
    const float* X = sel ? Xc : Xt;
    const int row0 = grow0 & (BB * LL - 1);
    const int koff = sel ? DD : 0;
    const int tid = threadIdx.x;
    const int r = tid >> 2, c0 = (tid & 3) * 12;

    float acc[12];
#pragma unroll
    for (int j = 0; j < 12; j++) acc[j] = 0.f;

    for (int k0 = 0; k0 < DD; k0 += 64) {
#pragma unroll
        for (int i = 0; i < 4; i++) {
            int id = tid + i * 128;
            int rr = id >> 4, qq = (id & 15) * 4;
            *(float4*)&Xs[rr][qq] = *(const float4*)&X[(size_t)(row0 + rr) * DD + k0 + qq];
        }
#pragma unroll
        for (int i = 0; i < 2; i++) {
            int id = tid + i * 128;
            int kr = id >> 2, qq = (id & 3) * 4;
            *(float4*)&Ws[kr][ 0 + qq] = *(const float4*)&W1[(size_t)(koff + k0 + kr) * EH + qq];
            *(float4*)&Ws[kr][16 + qq] = *(const float4*)&W2[(size_t)(koff + k0 + kr) * EH + qq];
            *(float4*)&Ws[kr][32 + qq] = *(const float4*)&W3[(size_t)(koff + k0 + kr) * EH + qq];
        }
        __syncthreads();
#pragma unroll
        for (int k = 0; k < 64; k++) {
            float x = Xs[r][k];
            float4 w0 = *(const float4*)&Ws[k][c0];
            float4 w1 = *(const float4*)&Ws[k][c0 + 4];
            float4 w2 = *(const float4*)&Ws[k][c0 + 8];
            acc[0] += x * w0.x;  acc[1] += x * w0.y;  acc[2]  += x * w0.z;  acc[3]  += x * w0.w;
            acc[4] += x * w1.x;  acc[5] += x * w1.y;  acc[6]  += x * w1.z;  acc[7]  += x * w1.w;
            acc[8] += x * w2.x;  acc[9] += x * w2.y;  acc[10] += x * w2.z;  acc[11] += x * w2.w;
        }
        __syncthreads();
    }

    const int row = row0 + r;
#pragma unroll
    for (int j = 0; j < 12; j++) {
        int cc = c0 + j;
        int m = cc >> 4, col = cc & 15;
        float* O = sel ? (m == 0 ? O1c : m == 1 ? O2c : O3c)
                       : (m == 0 ? O1t : m == 1 ? O2t : O3t);
        O[(size_t)row * EH + col] = acc[j];
    }
}

// ---------------- score + top-8: register keys, warp-hierarchical selection -------
// Each thread scores 8 candidates into registers. Warp-local top-8 via shuffle
// passes (no barriers), 8 warps x 8 -> 64 candidates; warp 0 merges to the global
// approx top-8 and the t8 threshold. Survivors (provable bound) get exact-erf
// rescoring and the same warp-hierarchical selection writes g_idx in order.
__global__ __launch_bounds__(256) void score_topk_kernel(
    const float* __restrict__ bs1, const float* __restrict__ Ws2, const float* __restrict__ bs2)
{
    __shared__ float a16[EH];
    __shared__ float w2s[EH];
    __shared__ unsigned long long s_wk[8][8];
    __shared__ int s_surv[SCAP];
    __shared__ int s_cnt;
    __shared__ float s_thr;

    int b = blockIdx.x >> 11, l = blockIdx.x & 2047;
    int tid = threadIdx.x;
    int warp = tid >> 5, lane = tid & 31;
    if (tid < EH) {
        a16[tid] = g_SA[((size_t)b * LL + l) * EH + tid] + bs1[tid];
        w2s[tid] = Ws2[tid];
    }
    __syncthreads();
    float aR[EH], wR[EH];
#pragma unroll
    for (int c = 0; c < EH; c++) { aR[c] = a16[c]; wR[c] = w2s[c]; }
    float bs2v = bs2[0];

    // phase A: approx scores -> registers
    float s8[8];
    unsigned long long k8[8];
#pragma unroll
    for (int i = 0; i < 8; i++) {
        int kk = tid + i * 256;
        const float4* bp = (const float4*)(g_SB + ((size_t)b * KK + kk) * EH);
        float4 b0 = bp[0], b1 = bp[1], b2 = bp[2], b3 = bp[3];
        float bv[EH] = {b0.x,b0.y,b0.z,b0.w, b1.x,b1.y,b1.z,b1.w,
                        b2.x,b2.y,b2.z,b2.w, b3.x,b3.y,b3.z,b3.w};
        float s = bs2v;
#pragma unroll
        for (int c = 0; c < EH; c++) s += gelu_approx(aR[c] + bv[c]) * wR[c];
        s8[i] = s;
        k8[i] = (((unsigned long long)flipf(s)) << 32) | (unsigned)(KK - 1 - kk);
    }

    // warp-local top-8 (barrier-free)
    {
        unsigned long long lm = k8[0]; int am = 0;
#pragma unroll
        for (int i = 1; i < 8; i++) if (k8[i] > lm) { lm = k8[i]; am = i; }
#pragma unroll
        for (int p = 0; p < 8; p++) {
            unsigned long long best = warp_max_ull(lm);
            if (lm == best && best != 0ull) {
                k8[am] = 0ull;
                lm = k8[0]; am = 0;
#pragma unroll
                for (int i = 1; i < 8; i++) if (k8[i] > lm) { lm = k8[i]; am = i; }
            }
            if (lane == 0) s_wk[warp][p] = best;
        }
    }
    __syncthreads();

    // warp 0: merge 64 -> approx top-8, compute threshold
    if (warp == 0) {
        unsigned long long ka = ((unsigned long long*)s_wk)[lane];
        unsigned long long kb = ((unsigned long long*)s_wk)[lane + 32];
        unsigned long long best = 0ull;
#pragma unroll
        for (int p = 0; p < 8; p++) {
            unsigned long long m = ka > kb ? ka : kb;
            best = warp_max_ull(m);
            if (ka == best) ka = 0ull; else if (kb == best) kb = 0ull;
        }
        if (lane == 0) {
            unsigned u = (unsigned)(best >> 32);
            float t8 = __uint_as_float((u & 0x80000000u) ? (u & 0x7fffffffu) : ~u);
            float sw = 0.f;
#pragma unroll
            for (int c = 0; c < EH; c++) sw += fabsf(w2s[c]);
            s_thr = t8 - (sw * 0.02f + 2e-3f);
            s_cnt = 0;
        }
    }
    __syncthreads();

    // survivor scan from register scores (approx top-8 included automatically)
    float thr = s_thr;
#pragma unroll
    for (int i = 0; i < 8; i++) {
        if (s8[i] >= thr) {
            int p = atomicAdd(&s_cnt, 1);
            if (p < SCAP) s_surv[p] = tid + i * 256;
        }
    }
    __syncthreads();
    int n = s_cnt;
    bool fb = (n > SCAP);

    // exact keys: survivors (normal) or all candidates (fallback)
    unsigned long long key = 0ull;
    if (!fb) {
        if (tid < n) {
            int kk = s_surv[tid];
            const float4* bp = (const float4*)(g_SB + ((size_t)b * KK + kk) * EH);
            float4 b0 = bp[0], b1 = bp[1], b2 = bp[2], b3 = bp[3];
            float bv[EH] = {b0.x,b0.y,b0.z,b0.w, b1.x,b1.y,b1.z,b1.w,
                            b2.x,b2.y,b2.z,b2.w, b3.x,b3.y,b3.z,b3.w};
            float s = bs2v;
#pragma unroll
            for (int c = 0; c < EH; c++) s += geluf(aR[c] + bv[c]) * wR[c];
            key = (((unsigned long long)flipf(s)) << 32) | (unsigned)(KK - 1 - kk);
        }
        // warp-local top-8 over single keys
#pragma unroll
        for (int p = 0; p < 8; p++) {
            unsigned long long best = warp_max_ull(key);
            if (key == best && best != 0ull) key = 0ull;
            if (lane == 0) s_wk[warp][p] = best;
        }
    } else {
        // fallback: exact rescore of everything, same register machinery
#pragma unroll
        for (int i = 0; i < 8; i++) {
            int kk = tid + i * 256;
            const float4* bp = (const float4*)(g_SB + ((size_t)b * KK + kk) * EH);
            float4 b0 = bp[0], b1 = bp[1], b2 = bp[2], b3 = bp[3];
            float bv[EH] = {b0.x,b0.y,b0.z,b0.w, b1.x,b1.y,b1.z,b1.w,
                            b2.x,b2.y,b2.z,b2.w, b3.x,b3.y,b3.z,b3.w};
            float s = bs2v;
#pragma unroll
            for (int c = 0; c < EH; c++) s += geluf(aR[c] + bv[c]) * wR[c];
            k8[i] = (((unsigned long long)flipf(s)) << 32) | (unsigned)(KK - 1 - kk);
        }
        unsigned long long lm = k8[0]; int am = 0;
#pragma unroll
        for (int i = 1; i < 8; i++) if (k8[i] > lm) { lm = k8[i]; am = i; }
#pragma unroll
        for (int p = 0; p < 8; p++) {
            unsigned long long best = warp_max_ull(lm);
            if (lm == best && best != 0ull) {
                k8[am] = 0ull;
                lm = k8[0]; am = 0;
#pragma unroll
                for (int i = 1; i < 8; i++) if (k8[i] > lm) { lm = k8[i]; am = i; }
            }
            if (lane == 0) s_wk[warp][p] = best;
        }
    }
    __syncthreads();

    // warp 0: final merge, write g_idx in order
    if (warp == 0) {
        unsigned long long ka = ((unsigned long long*)s_wk)[lane];
        unsigned long long kb = ((unsigned long long*)s_wk)[lane + 32];
#pragma unroll
        for (int p = 0; p < 8; p++) {
            unsigned long long m = ka > kb ? ka : kb;
            unsigned long long best = warp_max_ull(m);
            if (ka == best) ka = 0ull; else if (kb == best) kb = 0ull;
            if (lane == 0)
                g_idx[((size_t)b * LL + l) * WWIN + p] = KK - 1 - (int)(best & 0xffffffffu);
        }
    }
}

// ---------------- per-edge small params: gh (fp16), alpha ----------------
__global__ void edge_small_kernel(const float* __restrict__ bl1, const float* __restrict__ ba1,
                                  const float* __restrict__ Wa2, const float* __restrict__ ba2)
{
    int gw = (blockIdx.x * blockDim.x + threadIdx.x) >> 5;
    int ln = threadIdx.x & 31;
    if (gw >= BB * EE) return;
    int b = gw >> 14, e = gw & (EE - 1);
    int l = e >> 3, w = e & 7;
    int j = g_idx[((size_t)b * LL + l) * WWIN + w];
    int i = l;

    float hav = 0.f;
    if (ln < EH) {
        int c = ln;
        float hl = g_LA[((size_t)b * LL + i) * EH + c] + g_LB[((size_t)b * KK + j) * EH + c] + bl1[c];
        g_gh[(size_t)gw * EH + c] = __float2half(geluf(hl));
        float ha = g_AA[((size_t)b * LL + i) * EH + c] + g_AB[((size_t)b * KK + j) * EH + c] + ba1[c];
        hav = geluf(ha) * Wa2[c];
    }
#pragma unroll
    for (int o = 16; o; o >>= 1) hav += __shfl_xor_sync(0xffffffffu, hav, o);
    if (ln == 0) g_alpha[gw] = softplusf(hav + ba2[0]);
}

// ---------------- fused T=2 consensus: warp=head, 4 edges concurrent per warp -----
#define ITER_DYN_SMEM (8*LAMP*2 + 8*HH*HD*4)   // 65792 + 16384 = 82176 B
__global__ __launch_bounds__(256) void iter2_kernel(const float* __restrict__ step_sizes)
{
    extern __shared__ char dyn[];
    __half* s_lam = (__half*)dyn;                        // [8e] x LAMP halves
    float*  s_v   = (float*)(dyn + 8*LAMP*2);            // [8e][H][64]
    __shared__ float s_cs[8][32];
    __shared__ float s_sn[8][32];
    __shared__ float s_alpha[8];
    __shared__ int   s_idx[8];

    int b = blockIdx.x >> 11, l = blockIdx.x & 2047;
    int tid = threadIdx.x;
    int wi = tid >> 5, ln = tid & 31;
    int eg = ln >> 3, dg = ln & 7;

    {
        const float4* src = (const float4*)(g_LamH + ((size_t)b * EE + (size_t)l * 8) * NLAM);
        float4* dst = (float4*)s_lam;
#pragma unroll
        for (int i = 0; i < 16; i++) {
            int s = tid + i * 256;
            dst[s + (s >> 9) * 2] = src[s];
        }
    }
    {
        int e = wi;
        int j = g_idx[((size_t)b * LL + l) * WWIN + e];
        if (ln == 0) { s_idx[e] = j; s_alpha[e] = g_alpha[(size_t)b * EE + l * WWIN + e]; }
        float ang = (float)(l - j) * exp2f((float)ln * -0.41524101186092029f);
        s_cs[e][ln] = cosf(ang);
        s_sn[e][ln] = sinf(ang);
    }
    __syncthreads();
#pragma unroll
    for (int i = 0; i < 16; i++) {
        int gid = tid + i * 256;
        int e2 = gid >> 9, h2 = (gid >> 6) & 7, d = gid & 63;
        s_v[gid] = g_v[(((size_t)b * HH + h2) * KK + s_idx[e2]) * HD + d];
    }
    __syncthreads();

    size_t ubase = (((size_t)b * HH + wi) * LL + l) * HD;
    float4 u_lo = *(const float4*)&g_u[ubase + dg * 4];
    float4 u_hi = *(const float4*)&g_u[ubase + 32 + dg * 4];

#pragma unroll
    for (int t = 0; t < TT; t++) {
        float stp = softplusf(step_sizes[t * LL + l]);
        float al4[4] = {0.f,0.f,0.f,0.f}, ah4[4] = {0.f,0.f,0.f,0.f};
#pragma unroll
        for (int eb = 0; eb < 2; eb++) {
            int e = eb * 4 + eg;
            float4 cs4 = *(const float4*)&s_cs[e][dg * 4];
            float4 sn4 = *(const float4*)&s_sn[e][dg * 4];
            const float4* vp = (const float4*)&s_v[(e * HH + wi) * HD + dg * 4];
            float4 vlo = vp[0], vhi = vp[8];
            float dlo[4], dhi[4];
            dlo[0] = u_lo.x * cs4.x - u_hi.x * sn4.x - vlo.x;
            dlo[1] = u_lo.y * cs4.y - u_hi.y * sn4.y - vlo.y;
            dlo[2] = u_lo.z * cs4.z - u_hi.z * sn4.z - vlo.z;
            dlo[3] = u_lo.w * cs4.w - u_hi.w * sn4.w - vlo.w;
            dhi[0] = u_hi.x * cs4.x + u_lo.x * sn4.x - vhi.x;
            dhi[1] = u_hi.y * cs4.y + u_lo.y * sn4.y - vhi.y;
            dhi[2] = u_hi.z * cs4.z + u_lo.z * sn4.z - vhi.z;
            dhi[3] = u_hi.w * cs4.w + u_lo.w * sn4.w - vhi.w;
            float alp = s_alpha[e];
            float rl[4] = {0.f,0.f,0.f,0.f}, rh[4] = {0.f,0.f,0.f,0.f};
            const __half2* lp = (const __half2*)(s_lam + (size_t)e * LAMP + wi * RR * HD);
#pragma unroll
            for (int r = 0; r < RR; r++) {
                __half2 hl0 = lp[r * 32 + dg * 2], hl1 = lp[r * 32 + dg * 2 + 1];
                __half2 hh0 = lp[r * 32 + 16 + dg * 2], hh1 = lp[r * 32 + 16 + dg * 2 + 1];
                float2 f0 = __half22float2(hl0), f1 = __half22float2(hl1);
                float2 f2 = __half22float2(hh0), f3 = __half22float2(hh1);
                float p = f0.x * dlo[0] + f0.y * dlo[1] + f1.x * dlo[2] + f1.y * dlo[3]
                        + f2.x * dhi[0] + f2.y * dhi[1] + f3.x * dhi[2] + f3.y * dhi[3];
                p += __shfl_xor_sync(0xffffffffu, p, 1);
                p += __shfl_xor_sync(0xffffffffu, p, 2);
                p += __shfl_xor_sync(0xffffffffu, p, 4);
                rl[0] += p * f0.x; rl[1] += p * f0.y; rl[2] += p * f1.x; rl[3] += p * f1.y;
                rh[0] += p * f2.x; rh[1] += p * f2.y; rh[2] += p * f3.x; rh[3] += p * f3.y;
            }
#pragma unroll
            for (int i = 0; i < 4; i++) {
                al4[i] += alp * dlo[i] + rl[i];
                ah4[i] += alp * dhi[i] + rh[i];
            }
        }
#pragma unroll
        for (int i = 0; i < 4; i++) {
            al4[i] += __shfl_xor_sync(0xffffffffu, al4[i], 8);
            al4[i] += __shfl_xor_sync(0xffffffffu, al4[i], 16);
            ah4[i] += __shfl_xor_sync(0xffffffffu, ah4[i], 8);
            ah4[i] += __shfl_xor_sync(0xffffffffu, ah4[i], 16);
        }
        u_lo.x -= stp * al4[0]; u_lo.y -= stp * al4[1];
        u_lo.z -= stp * al4[2]; u_lo.w -= stp * al4[3];
        u_hi.x -= stp * ah4[0]; u_hi.y -= stp * ah4[1];
        u_hi.z -= stp * ah4[2]; u_hi.w -= stp * ah4[3];
    }
    if (eg == 0) {
        *(float4*)&g_u[ubase + dg * 4] = u_lo;
        *(float4*)&g_u[ubase + 32 + dg * 4] = u_hi;
    }
}

// ---------------- launch ----------------
extern "C" void kernel_launch(void* const* d_in, const int* in_sizes, int n_in,
                              void* d_out, int out_size)
{
    const float* target = (const float*)d_in[0];
    const float* context= (const float*)d_in[1];
    const float* Wt  = (const float*)d_in[2];
    const float* bt  = (const float*)d_in[3];
    const float* Wc  = (const float*)d_in[4];
    const float* bc  = (const float*)d_in[5];
    const float* Ws1 = (const float*)d_in[6];
    const float* bs1 = (const float*)d_in[7];
    const float* Ws2 = (const float*)d_in[8];
    const float* bs2 = (const float*)d_in[9];
    const float* Wa1 = (const float*)d_in[10];
    const float* ba1 = (const float*)d_in[11];
    const float* Wa2 = (const float*)d_in[12];
    const float* ba2 = (const float*)d_in[13];
    const float* Wl1 = (const float*)d_in[14];
    const float* bl1 = (const float*)d_in[15];
    const float* Wl2 = (const float*)d_in[16];
    const float* bl2 = (const float*)d_in[17];
    const float* step_sizes = (const float*)d_in[18];
    const float* Wo  = (const float*)d_in[19];
    const float* bo  = (const float*)d_in[20];

    float *pu, *pv, *pSA, *pSB, *pAA, *pAB, *pLA, *pLB;
    cudaGetSymbolAddress((void**)&pu,  g_u);
    cudaGetSymbolAddress((void**)&pv,  g_v);
    cudaGetSymbolAddress((void**)&pSA, g_SA);
    cudaGetSymbolAddress((void**)&pSB, g_SB);
    cudaGetSymbolAddress((void**)&pAA, g_AA);
    cudaGetSymbolAddress((void**)&pAB, g_AB);
    cudaGetSymbolAddress((void**)&pLA, g_LA);
    cudaGetSymbolAddress((void**)&pLB, g_LB);

    cudaFuncSetAttribute(iter2_kernel, cudaFuncAttributeMaxDynamicSharedMemorySize,
                         ITER_DYN_SMEM);

    const int Mrows = BB * LL;  // 4096

    // u and v projections in one launch (M = 8192, second half uses Wc/bc -> v)
    gemm32_kernel<<<dim3(DD/64, (2*Mrows)/128), 256>>>(
        target, Wt, bt, pu, 2*Mrows, DD, DD, 0, 1, context, Wc, bc, pv, Mrows);

    prep_wl2_kernel<<<(NLAM + 255) / 256, 256>>>(Wl2);

    // separable 16-dim projections (exact fp32 — feeds top-k)
    proj_kernel<<<(2*Mrows)/32, 128>>>(target, context, Ws1, Wa1, Wl1,
                                       pSA, pAA, pLA, pSB, pAB, pLB);

    // scores + top-8 (approx prune, exact rescue, register-resident selection)
    score_topk_kernel<<<BB * LL, 256>>>(bs1, Ws2, bs2);

    edge_small_kernel<<<(BB * EE * 32 + 255) / 256, 256>>>(bl1, ba1, Wa2, ba2);

    lam_mma_kernel<<<dim3(NLAM/64, (BB*EE)/128), 256>>>(bl2);

    iter2_kernel<<<BB * LL, 256, ITER_DYN_SMEM>>>(step_sizes);

    gemm32_kernel<<<dim3(DD/64, Mrows/128), 256>>>(
        pu, Wo, bo, (float*)d_out, Mrows, DD, DD, 1, 0,
        nullptr, nullptr, nullptr, nullptr, 0);
}

// round 6
// speedup vs baseline: 2.1318x; 1.1491x over previous
#include <cuda_runtime.h>
#include <cuda_fp16.h>
#include <cstdint>

// Problem constants
#define BB 2
#define LL 2048
#define KK 2048
#define DD 512
#define HH 8
#define HD 64
#define RR 8
#define WWIN 8
#define EE (LL*WWIN)          // 16384 edges per batch
#define EH 16
#define TT 2
#define NLAM (HH*RR*HD)       // 4096
#define SCAP 256              // survivor cap in score kernel
#define LAMP 4112             // padded halves per edge chunk in iter2 smem (4096+16)

// ---------------- scratch (allocation-free: static device globals) ----------------
__device__ float  g_u [BB*HH*LL*HD];          // [B,H,L,HD]
__device__ float  g_v [BB*HH*KK*HD];          // [B,H,K,HD]
__device__ float  g_SA[BB*LL*EH];
__device__ float  g_SB[BB*KK*EH];
__device__ __half g_SBh[BB*KK*EH];            // fp16 copy for approx scoring
__device__ float  g_AA[BB*LL*EH];
__device__ float  g_AB[BB*KK*EH];
__device__ float  g_LA[BB*LL*EH];
__device__ float  g_LB[BB*KK*EH];
__device__ int    g_idx[BB*LL*WWIN];
__device__ __half g_Wl2h[NLAM*EH];            // Wl2 transposed [n][k] fp16

// ---------------- helpers ----------------
__device__ __forceinline__ float geluf(float x){
    return 0.5f * x * (1.0f + erff(x * 0.7071067811865475244f));
}
__device__ __forceinline__ float softplusf(float x){
    return (x > 20.f) ? x : log1pf(expf(x));
}
__device__ __forceinline__ float tf32_rna(float x){
    uint32_t u;
    asm("cvt.rna.tf32.f32 %0, %1;" : "=r"(u) : "f"(x));
    return __uint_as_float(u);
}
__device__ __forceinline__ unsigned flipf(float s){
    unsigned u = __float_as_uint(s);
    return (u & 0x80000000u) ? ~u : (u | 0x80000000u);
}
__device__ __forceinline__ __half2 tanh2(__half2 x){
    uint32_t r, a = *(uint32_t*)&x;
    asm("tanh.approx.f16x2 %0, %1;" : "=r"(r) : "r"(a));
    return *(__half2*)&r;
}
__device__ __forceinline__ void mma_tf32(float* d, const uint32_t* a, const uint32_t* b){
    asm("mma.sync.aligned.m16n8k8.row.col.f32.tf32.tf32.f32 "
        "{%0,%1,%2,%3}, {%4,%5,%6,%7}, {%8,%9}, {%0,%1,%2,%3};"
        : "+f"(d[0]), "+f"(d[1]), "+f"(d[2]), "+f"(d[3])
        : "r"(a[0]), "r"(a[1]), "r"(a[2]), "r"(a[3]), "r"(b[0]), "r"(b[1]));
}
__device__ __forceinline__ void mma_f16(float* d, uint32_t a0, uint32_t a1, uint32_t a2,
                                        uint32_t a3, uint32_t b0, uint32_t b1){
    asm("mma.sync.aligned.m16n8k16.row.col.f32.f16.f16.f32 "
        "{%0,%1,%2,%3}, {%4,%5,%6,%7}, {%8,%9}, {%0,%1,%2,%3};"
        : "+f"(d[0]), "+f"(d[1]), "+f"(d[2]), "+f"(d[3])
        : "r"(a0), "r"(a1), "r"(a2), "r"(a3), "r"(b0), "r"(b1));
}
__device__ __forceinline__ unsigned long long warp_max_ull(unsigned long long v){
#pragma unroll
    for (int o = 16; o; o >>= 1) {
        unsigned long long w = __shfl_xor_sync(0xffffffffu, v, o);
        if (w > v) v = w;
    }
    return v;
}

// ---------------- tf32 tensor-core GEMM: C = A[MxK] @ W[KxN] + bias ----------------
__global__ __launch_bounds__(256) void gemm32_kernel(
    const float* A, const float* W, const float* bias, float* C,
    int M, int N, int Kd, int aload, int smode,
    const float* A2, const float* W2, const float* bias2, float* C2, int halfM)
{
    __shared__ float As[128][36];
    __shared__ float Bs[32][72];
    int bm = blockIdx.y * 128;
    const int bn = blockIdx.x * 64;
    if (halfM && bm >= halfM) { A = A2; W = W2; bias = bias2; C = C2; bm -= halfM; }
    const int tid  = threadIdx.x;
    const int warp = tid >> 5, lane = tid & 31;
    const int wm = warp & 3, wn = warp >> 2;
    const int q = lane >> 2, c = lane & 3;

    float d[2][4][4];
#pragma unroll
    for (int mt = 0; mt < 2; mt++)
#pragma unroll
        for (int nt = 0; nt < 4; nt++)
#pragma unroll
            for (int i = 0; i < 4; i++) d[mt][nt][i] = 0.f;

    for (int k0 = 0; k0 < Kd; k0 += 32) {
#pragma unroll
        for (int i = 0; i < 4; i++) {
            int id = tid + i * 256;
            int m = id >> 3, kq = (id & 7) * 4;
            float4 v;
            if (aload) {
                int mm = bm + m; int b = mm >> 11, l = mm & 2047;
                int k = k0 + kq; int h = k >> 6, hd = k & 63;
                v = *(const float4*)&A[(((size_t)b * HH + h) * LL + l) * HD + hd];
            } else {
                v = *(const float4*)&A[(size_t)(bm + m) * Kd + k0 + kq];
            }
            float4 t = make_float4(tf32_rna(v.x), tf32_rna(v.y), tf32_rna(v.z), tf32_rna(v.w));
            *(float4*)&As[m][kq] = t;
        }
#pragma unroll
        for (int i = 0; i < 2; i++) {
            int id = tid + i * 256;
            int kk = id >> 4, nq = (id & 15) * 4;
            float4 v = *(const float4*)&W[(size_t)(k0 + kk) * N + bn + nq];
            float4 t = make_float4(tf32_rna(v.x), tf32_rna(v.y), tf32_rna(v.z), tf32_rna(v.w));
            *(float4*)&Bs[kk][nq] = t;
        }
        __syncthreads();
#pragma unroll
        for (int k8 = 0; k8 < 4; k8++) {
            uint32_t a[2][4], b[4][2];
#pragma unroll
            for (int mt = 0; mt < 2; mt++) {
                int r0 = wm * 32 + mt * 16 + q;
                a[mt][0] = __float_as_uint(As[r0    ][k8 * 8 + c]);
                a[mt][1] = __float_as_uint(As[r0 + 8][k8 * 8 + c]);
                a[mt][2] = __float_as_uint(As[r0    ][k8 * 8 + c + 4]);
                a[mt][3] = __float_as_uint(As[r0 + 8][k8 * 8 + c + 4]);
            }
#pragma unroll
            for (int nt = 0; nt < 4; nt++) {
                int cn = wn * 32 + nt * 8 + q;
                b[nt][0] = __float_as_uint(Bs[k8 * 8 + c    ][cn]);
                b[nt][1] = __float_as_uint(Bs[k8 * 8 + c + 4][cn]);
            }
#pragma unroll
            for (int mt = 0; mt < 2; mt++)
#pragma unroll
                for (int nt = 0; nt < 4; nt++)
                    mma_tf32(d[mt][nt], a[mt], b[nt]);
        }
        __syncthreads();
    }

#pragma unroll
    for (int mt = 0; mt < 2; mt++) {
        int gm0 = bm + wm * 32 + mt * 16 + q;
#pragma unroll
        for (int nt = 0; nt < 4; nt++) {
            int gn = bn + wn * 32 + nt * 8 + 2 * c;
            float b0 = __ldg(&bias[gn]), b1 = __ldg(&bias[gn + 1]);
            float v0 = d[mt][nt][0] + b0, v1 = d[mt][nt][1] + b1;
            float v2 = d[mt][nt][2] + b0, v3 = d[mt][nt][3] + b1;
            if (smode == 1) {
                int bb = gm0 >> 11, l = gm0 & 2047, h = gn >> 6, hd = gn & 63;
                float* p0 = &C[(((size_t)bb * HH + h) * LL + l) * HD + hd];
                p0[0] = v0; p0[1] = v1;
                float* p2 = &C[(((size_t)bb * HH + h) * LL + (l + 8)) * HD + hd];
                p2[0] = v2; p2[1] = v3;
            } else {
                *(float2*)&C[(size_t)gm0 * N + gn] = make_float2(v0, v1);
                *(float2*)&C[(size_t)(gm0 + 8) * N + gn] = make_float2(v2, v3);
            }
        }
    }
}

// ---------------- Wl2 transpose+convert: [16][4096] f32 -> [4096][16] f16 ----------
__global__ void prep_wl2_kernel(const float* __restrict__ Wl2)
{
    int n = blockIdx.x * blockDim.x + threadIdx.x;
    if (n >= NLAM) return;
#pragma unroll
    for (int k = 0; k < EH; k++)
        g_Wl2h[n * EH + k] = __float2half(Wl2[(size_t)k * NLAM + n]);
}

// ---------------- 512->48 projection (both inputs), 12 cols/thread ----------------
// Also emits SB (score projection of context) in fp16 for the approx score phase.
__global__ __launch_bounds__(128) void proj_kernel(
    const float* __restrict__ Xt, const float* __restrict__ Xc,
    const float* __restrict__ W1, const float* __restrict__ W2, const float* __restrict__ W3,
    float* __restrict__ O1t, float* __restrict__ O2t, float* __restrict__ O3t,
    float* __restrict__ O1c, float* __restrict__ O2c, float* __restrict__ O3c)
{
    __shared__ float Xs[32][68];
    __shared__ float Ws[64][52];
    const int grow0 = blockIdx.x * 32;
    const int sel = grow0 >= (BB * LL);
    const float* X = sel ? Xc : Xt;
    const int row0 = grow0 & (BB * LL - 1);
    const int koff = sel ? DD : 0;
    const int tid = threadIdx.x;
    const int r = tid >> 2, c0 = (tid & 3) * 12;

    float acc[12];
#pragma unroll
    for (int j = 0; j < 12; j++) acc[j] = 0.f;

    for (int k0 = 0; k0 < DD; k0 += 64) {
#pragma unroll
        for (int i = 0; i < 4; i++) {
            int id = tid + i * 128;
            int rr = id >> 4, qq = (id & 15) * 4;
            *(float4*)&Xs[rr][qq] = *(const float4*)&X[(size_t)(row0 + rr) * DD + k0 + qq];
        }
#pragma unroll
        for (int i = 0; i < 2; i++) {
            int id = tid + i * 128;
            int kr = id >> 2, qq = (id & 3) * 4;
            *(float4*)&Ws[kr][ 0 + qq] = *(const float4*)&W1[(size_t)(koff + k0 + kr) * EH + qq];
            *(float4*)&Ws[kr][16 + qq] = *(const float4*)&W2[(size_t)(koff + k0 + kr) * EH + qq];
            *(float4*)&Ws[kr][32 + qq] = *(const float4*)&W3[(size_t)(koff + k0 + kr) * EH + qq];
        }
        __syncthreads();
#pragma unroll
        for (int k = 0; k < 64; k++) {
            float x = Xs[r][k];
            float4 w0 = *(const float4*)&Ws[k][c0];
            float4 w1 = *(const float4*)&Ws[k][c0 + 4];
            float4 w2 = *(const float4*)&Ws[k][c0 + 8];
            acc[0] += x * w0.x;  acc[1] += x * w0.y;  acc[2]  += x * w0.z;  acc[3]  += x * w0.w;
            acc[4] += x * w1.x;  acc[5] += x * w1.y;  acc[6]  += x * w1.z;  acc[7]  += x * w1.w;
            acc[8] += x * w2.x;  acc[9] += x * w2.y;  acc[10] += x * w2.z;  acc[11] += x * w2.w;
        }
        __syncthreads();
    }

    const int row = row0 + r;
#pragma unroll
    for (int j = 0; j < 12; j++) {
        int cc = c0 + j;
        int m = cc >> 4, col = cc & 15;
        float* O = sel ? (m == 0 ? O1c : m == 1 ? O2c : O3c)
                       : (m == 0 ? O1t : m == 1 ? O2t : O3t);
        O[(size_t)row * EH + col] = acc[j];
        if (sel && m == 0)
            g_SBh[(size_t)row * EH + col] = __float2half(acc[j]);
    }
}

// ---------------- score + top-8: half2 approx prune + exact rescue ----------------
__global__ __launch_bounds__(256) void score_topk_kernel(
    const float* __restrict__ bs1, const float* __restrict__ Ws2, const float* __restrict__ bs2)
{
    __shared__ float a16[EH];
    __shared__ float w2s[EH];
    __shared__ __half2 a2h[8];
    __shared__ __half2 w2h[8];
    __shared__ unsigned long long s_wk[8][8];
    __shared__ int s_surv[SCAP];
    __shared__ int s_cnt;
    __shared__ float s_thr;

    int b = blockIdx.x >> 11, l = blockIdx.x & 2047;
    int tid = threadIdx.x;
    int warp = tid >> 5, lane = tid & 31;
    if (tid < EH) {
        a16[tid] = g_SA[((size_t)b * LL + l) * EH + tid] + bs1[tid];
        w2s[tid] = Ws2[tid];
    }
    __syncthreads();
    if (tid < 8) {
        a2h[tid] = __floats2half2_rn(a16[2 * tid], a16[2 * tid + 1]);
        w2h[tid] = __floats2half2_rn(w2s[2 * tid], w2s[2 * tid + 1]);
    }
    __syncthreads();
    float aR[EH], wR[EH];
#pragma unroll
    for (int c = 0; c < EH; c++) { aR[c] = a16[c]; wR[c] = w2s[c]; }
    __half2 aH[8], wH[8];
#pragma unroll
    for (int c = 0; c < 8; c++) { aH[c] = a2h[c]; wH[c] = w2h[c]; }
    float bs2v = bs2[0];
    const __half2 C1 = __float2half2_rn(0.0356774081f);   // 0.79788456*0.044715
    const __half2 C0 = __float2half2_rn(0.7978845608f);
    const __half2 H5 = __float2half2_rn(0.5f);

    // phase A: half2 approx scores -> registers
    float s8[8];
    unsigned long long k8[8];
#pragma unroll
    for (int i = 0; i < 8; i++) {
        int kk = tid + i * 256;
        const uint4* bp = (const uint4*)(g_SBh + ((size_t)b * KK + kk) * EH);
        uint4 r0 = bp[0], r1 = bp[1];
        uint32_t bw[8] = {r0.x, r0.y, r0.z, r0.w, r1.x, r1.y, r1.z, r1.w};
        __half2 acc = __float2half2_rn(0.f);
#pragma unroll
        for (int c = 0; c < 8; c++) {
            __half2 h  = __hadd2(aH[c], *(__half2*)&bw[c]);
            __half2 p  = __hmul2(h, h);
            __half2 qq = __hfma2(p, C1, C0);
            __half2 t  = __hmul2(h, qq);
            __half2 th = tanh2(t);
            __half2 hh = __hmul2(h, H5);
            __half2 rs = __hfma2(hh, th, hh);
            acc = __hfma2(rs, wH[c], acc);
        }
        float2 f = __half22float2(acc);
        float s = f.x + f.y + bs2v;
        s8[i] = s;
        k8[i] = (((unsigned long long)flipf(s)) << 32) | (unsigned)(KK - 1 - kk);
    }

    // warp-local top-8 (barrier-free)
    {
        unsigned long long lm = k8[0]; int am = 0;
#pragma unroll
        for (int i = 1; i < 8; i++) if (k8[i] > lm) { lm = k8[i]; am = i; }
#pragma unroll
        for (int p = 0; p < 8; p++) {
            unsigned long long best = warp_max_ull(lm);
            if (lm == best && best != 0ull) {
                k8[am] = 0ull;
                lm = k8[0]; am = 0;
#pragma unroll
                for (int i = 1; i < 8; i++) if (k8[i] > lm) { lm = k8[i]; am = i; }
            }
            if (lane == 0) s_wk[warp][p] = best;
        }
    }
    __syncthreads();

    // warp 0: merge 64 -> approx top-8, compute threshold (provable error margin)
    if (warp == 0) {
        unsigned long long ka = ((unsigned long long*)s_wk)[lane];
        unsigned long long kb = ((unsigned long long*)s_wk)[lane + 32];
        unsigned long long best = 0ull;
#pragma unroll
        for (int p = 0; p < 8; p++) {
            unsigned long long m = ka > kb ? ka : kb;
            best = warp_max_ull(m);
            if (ka == best) ka = 0ull; else if (kb == best) kb = 0ull;
        }
        if (lane == 0) {
            unsigned u = (unsigned)(best >> 32);
            float t8 = __uint_as_float((u & 0x80000000u) ? (u & 0x7fffffffu) : ~u);
            float sw = 0.f;
#pragma unroll
            for (int c = 0; c < EH; c++) sw += fabsf(w2s[c]);
            s_thr = t8 - (sw * 0.03f + 0.06f);
            s_cnt = 0;
        }
    }
    __syncthreads();

    // survivor scan from register scores
    float thr = s_thr;
#pragma unroll
    for (int i = 0; i < 8; i++) {
        if (s8[i] >= thr) {
            int p = atomicAdd(&s_cnt, 1);
            if (p < SCAP) s_surv[p] = tid + i * 256;
        }
    }
    __syncthreads();
    int n = s_cnt;
    bool fb = (n > SCAP);

    unsigned long long key = 0ull;
    if (!fb) {
        if (tid < n) {
            int kk = s_surv[tid];
            const float4* bp = (const float4*)(g_SB + ((size_t)b * KK + kk) * EH);
            float4 b0 = bp[0], b1 = bp[1], b2 = bp[2], b3 = bp[3];
            float bv[EH] = {b0.x,b0.y,b0.z,b0.w, b1.x,b1.y,b1.z,b1.w,
                            b2.x,b2.y,b2.z,b2.w, b3.x,b3.y,b3.z,b3.w};
            float s = bs2v;
#pragma unroll
            for (int c = 0; c < EH; c++) s += geluf(aR[c] + bv[c]) * wR[c];
            key = (((unsigned long long)flipf(s)) << 32) | (unsigned)(KK - 1 - kk);
        }
#pragma unroll
        for (int p = 0; p < 8; p++) {
            unsigned long long best = warp_max_ull(key);
            if (key == best && best != 0ull) key = 0ull;
            if (lane == 0) s_wk[warp][p] = best;
        }
    } else {
        // fallback: exact rescore of everything
#pragma unroll
        for (int i = 0; i < 8; i++) {
            int kk = tid + i * 256;
            const float4* bp = (const float4*)(g_SB + ((size_t)b * KK + kk) * EH);
            float4 b0 = bp[0], b1 = bp[1], b2 = bp[2], b3 = bp[3];
            float bv[EH] = {b0.x,b0.y,b0.z,b0.w, b1.x,b1.y,b1.z,b1.w,
                            b2.x,b2.y,b2.z,b2.w, b3.x,b3.y,b3.z,b3.w};
            float s = bs2v;
#pragma unroll
            for (int c = 0; c < EH; c++) s += geluf(aR[c] + bv[c]) * wR[c];
            k8[i] = (((unsigned long long)flipf(s)) << 32) | (unsigned)(KK - 1 - kk);
        }
        unsigned long long lm = k8[0]; int am = 0;
#pragma unroll
        for (int i = 1; i < 8; i++) if (k8[i] > lm) { lm = k8[i]; am = i; }
#pragma unroll
        for (int p = 0; p < 8; p++) {
            unsigned long long best = warp_max_ull(lm);
            if (lm == best && best != 0ull) {
                k8[am] = 0ull;
                lm = k8[0]; am = 0;
#pragma unroll
                for (int i = 1; i < 8; i++) if (k8[i] > lm) { lm = k8[i]; am = i; }
            }
            if (lane == 0) s_wk[warp][p] = best;
        }
    }
    __syncthreads();

    if (warp == 0) {
        unsigned long long ka = ((unsigned long long*)s_wk)[lane];
        unsigned long long kb = ((unsigned long long*)s_wk)[lane + 32];
#pragma unroll
        for (int p = 0; p < 8; p++) {
            unsigned long long m = ka > kb ? ka : kb;
            unsigned long long best = warp_max_ull(m);
            if (ka == best) ka = 0ull; else if (kb == best) kb = 0ull;
            if (lane == 0)
                g_idx[((size_t)b * LL + l) * WWIN + p] = KK - 1 - (int)(best & 0xffffffffu);
        }
    }
}

// ---------------- fused consensus: gh/alpha + in-block Lam MMA + T=2 iterations ---
// Block = (b,l). Warp wi = head. Lam never touches DRAM: generated in smem from
// gh[8x16] @ Wl2h[16x4096] with m16n8k16 (8 valid A rows), fused 64-chunk norm.
#define ITER_DYN_SMEM (8*LAMP*2 + 8*HH*HD*4)   // 65792 + 16384 = 82176 B
__global__ __launch_bounds__(256) void iter2_kernel(
    const float* __restrict__ step_sizes, const float* __restrict__ bl1,
    const float* __restrict__ ba1, const float* __restrict__ Wa2,
    const float* __restrict__ ba2, const float* __restrict__ bl2)
{
    extern __shared__ char dyn[];
    __half* s_lam = (__half*)dyn;                        // [8e] x LAMP halves
    float*  s_v   = (float*)(dyn + 8*LAMP*2);            // [8e][H][64]
    __shared__ float s_cs[8][32];
    __shared__ float s_sn[8][32];
    __shared__ float s_alpha[8];
    __shared__ int   s_idx[8];
    __shared__ __half s_gh[8][EH];

    int b = blockIdx.x >> 11, l = blockIdx.x & 2047;
    int tid = threadIdx.x;
    int wi = tid >> 5, ln = tid & 31;
    int eg = ln >> 3, dg = ln & 7;
    int q = ln >> 2, cq = ln & 3;

    // per-edge small params: warp e owns edge e
    {
        int e = wi;
        int j = g_idx[((size_t)b * LL + l) * WWIN + e];
        if (ln == 0) s_idx[e] = j;
        float hav = 0.f;
        if (ln < EH) {
            int c = ln;
            float hl = g_LA[((size_t)b * LL + l) * EH + c]
                     + g_LB[((size_t)b * KK + j) * EH + c] + bl1[c];
            s_gh[e][c] = __float2half(geluf(hl));
            float ha = g_AA[((size_t)b * LL + l) * EH + c]
                     + g_AB[((size_t)b * KK + j) * EH + c] + ba1[c];
            hav = geluf(ha) * Wa2[c];
        }
#pragma unroll
        for (int o = 16; o; o >>= 1) hav += __shfl_xor_sync(0xffffffffu, hav, o);
        if (ln == 0) s_alpha[e] = softplusf(hav + ba2[0]);
        float ang = (float)(l - j) * exp2f((float)ln * -0.41524101186092029f);
        s_cs[e][ln] = cosf(ang);
        s_sn[e][ln] = sinf(ang);
    }
    __syncthreads();

    // stage gathered v rows
#pragma unroll
    for (int i = 0; i < 16; i++) {
        int gid = tid + i * 256;
        int e2 = gid >> 9, h2 = (gid >> 6) & 7, d = gid & 63;
        s_v[gid] = g_v[(((size_t)b * HH + h2) * KK + s_idx[e2]) * HD + d];
    }

    // generate Lam for head wi: rows = edges (A rows 0-7 valid), 512 cols per warp
    {
        uint32_t A0 = *(const uint32_t*)&s_gh[q][2 * cq];
        uint32_t A2 = *(const uint32_t*)&s_gh[q][2 * cq + 8];
        uint32_t Z = 0u;
#pragma unroll
        for (int rr = 0; rr < 8; rr++) {
            float v0a[8], v1a[8];
            float ssq = 0.f;
#pragma unroll
            for (int ii = 0; ii < 8; ii++) {
                int colq = wi * 512 + (rr * 8 + ii) * 8 + q;       // B col this thread
                const uint32_t* bp = (const uint32_t*)(g_Wl2h + (size_t)colq * EH);
                uint32_t b0 = bp[cq], b1 = bp[cq + 4];
                float dd[4] = {0.f, 0.f, 0.f, 0.f};
                mma_f16(dd, A0, Z, A2, Z, b0, b1);
                int ncol = wi * 512 + (rr * 8 + ii) * 8 + 2 * cq;  // output cols (edge q)
                float2 bb = *(const float2*)&bl2[ncol];
                v0a[ii] = dd[0] + bb.x;
                v1a[ii] = dd[1] + bb.y;
                ssq += v0a[ii] * v0a[ii] + v1a[ii] * v1a[ii];
            }
            ssq += __shfl_xor_sync(0xffffffffu, ssq, 1);
            ssq += __shfl_xor_sync(0xffffffffu, ssq, 2);
            float sc = 1.f / fmaxf(sqrtf(ssq), 1e-12f);
#pragma unroll
            for (int ii = 0; ii < 8; ii++) {
                int ncol = wi * 512 + (rr * 8 + ii) * 8 + 2 * cq;
                *(__half2*)&s_lam[(size_t)q * LAMP + ncol] =
                    __floats2half2_rn(v0a[ii] * sc, v1a[ii] * sc);
            }
        }
    }
    __syncthreads();

    size_t ubase = (((size_t)b * HH + wi) * LL + l) * HD;
    float4 u_lo = *(const float4*)&g_u[ubase + dg * 4];
    float4 u_hi = *(const float4*)&g_u[ubase + 32 + dg * 4];

#pragma unroll
    for (int t = 0; t < TT; t++) {
        float stp = softplusf(step_sizes[t * LL + l]);
        float al4[4] = {0.f,0.f,0.f,0.f}, ah4[4] = {0.f,0.f,0.f,0.f};
#pragma unroll
        for (int eb = 0; eb < 2; eb++) {
            int e = eb * 4 + eg;
            float4 cs4 = *(const float4*)&s_cs[e][dg * 4];
            float4 sn4 = *(const float4*)&s_sn[e][dg * 4];
            const float4* vp = (const float4*)&s_v[(e * HH + wi) * HD + dg * 4];
            float4 vlo = vp[0], vhi = vp[8];
            float dlo[4], dhi[4];
            dlo[0] = u_lo.x * cs4.x - u_hi.x * sn4.x - vlo.x;
            dlo[1] = u_lo.y * cs4.y - u_hi.y * sn4.y - vlo.y;
            dlo[2] = u_lo.z * cs4.z - u_hi.z * sn4.z - vlo.z;
            dlo[3] = u_lo.w * cs4.w - u_hi.w * sn4.w - vlo.w;
            dhi[0] = u_hi.x * cs4.x + u_lo.x * sn4.x - vhi.x;
            dhi[1] = u_hi.y * cs4.y + u_lo.y * sn4.y - vhi.y;
            dhi[2] = u_hi.z * cs4.z + u_lo.z * sn4.z - vhi.z;
            dhi[3] = u_hi.w * cs4.w + u_lo.w * sn4.w - vhi.w;
            float alp = s_alpha[e];
            float rl[4] = {0.f,0.f,0.f,0.f}, rh[4] = {0.f,0.f,0.f,0.f};
            const __half2* lp = (const __half2*)(s_lam + (size_t)e * LAMP + wi * RR * HD);
#pragma unroll
            for (int r = 0; r < RR; r++) {
                __half2 hl0 = lp[r * 32 + dg * 2], hl1 = lp[r * 32 + dg * 2 + 1];
                __half2 hh0 = lp[r * 32 + 16 + dg * 2], hh1 = lp[r * 32 + 16 + dg * 2 + 1];
                float2 f0 = __half22float2(hl0), f1 = __half22float2(hl1);
                float2 f2 = __half22float2(hh0), f3 = __half22float2(hh1);
                float p = f0.x * dlo[0] + f0.y * dlo[1] + f1.x * dlo[2] + f1.y * dlo[3]
                        + f2.x * dhi[0] + f2.y * dhi[1] + f3.x * dhi[2] + f3.y * dhi[3];
                p += __shfl_xor_sync(0xffffffffu, p, 1);
                p += __shfl_xor_sync(0xffffffffu, p, 2);
                p += __shfl_xor_sync(0xffffffffu, p, 4);
                rl[0] += p * f0.x; rl[1] += p * f0.y; rl[2] += p * f1.x; rl[3] += p * f1.y;
                rh[0] += p * f2.x; rh[1] += p * f2.y; rh[2] += p * f3.x; rh[3] += p * f3.y;
            }
#pragma unroll
            for (int i = 0; i < 4; i++) {
                al4[i] += alp * dlo[i] + rl[i];
                ah4[i] += alp * dhi[i] + rh[i];
            }
        }
#pragma unroll
        for (int i = 0; i < 4; i++) {
            al4[i] += __shfl_xor_sync(0xffffffffu, al4[i], 8);
            al4[i] += __shfl_xor_sync(0xffffffffu, al4[i], 16);
            ah4[i] += __shfl_xor_sync(0xffffffffu, ah4[i], 8);
            ah4[i] += __shfl_xor_sync(0xffffffffu, ah4[i], 16);
        }
        u_lo.x -= stp * al4[0]; u_lo.y -= stp * al4[1];
        u_lo.z -= stp * al4[2]; u_lo.w -= stp * al4[3];
        u_hi.x -= stp * ah4[0]; u_hi.y -= stp * ah4[1];
        u_hi.z -= stp * ah4[2]; u_hi.w -= stp * ah4[3];
    }
    if (eg == 0) {
        *(float4*)&g_u[ubase + dg * 4] = u_lo;
        *(float4*)&g_u[ubase + 32 + dg * 4] = u_hi;
    }
}

// ---------------- launch ----------------
extern "C" void kernel_launch(void* const* d_in, const int* in_sizes, int n_in,
                              void* d_out, int out_size)
{
    const float* target = (const float*)d_in[0];
    const float* context= (const float*)d_in[1];
    const float* Wt  = (const float*)d_in[2];
    const float* bt  = (const float*)d_in[3];
    const float* Wc  = (const float*)d_in[4];
    const float* bc  = (const float*)d_in[5];
    const float* Ws1 = (const float*)d_in[6];
    const float* bs1 = (const float*)d_in[7];
    const float* Ws2 = (const float*)d_in[8];
    const float* bs2 = (const float*)d_in[9];
    const float* Wa1 = (const float*)d_in[10];
    const float* ba1 = (const float*)d_in[11];
    const float* Wa2 = (const float*)d_in[12];
    const float* ba2 = (const float*)d_in[13];
    const float* Wl1 = (const float*)d_in[14];
    const float* bl1 = (const float*)d_in[15];
    const float* Wl2 = (const float*)d_in[16];
    const float* bl2 = (const float*)d_in[17];
    const float* step_sizes = (const float*)d_in[18];
    const float* Wo  = (const float*)d_in[19];
    const float* bo  = (const float*)d_in[20];

    float *pu, *pv, *pSA, *pSB, *pAA, *pAB, *pLA, *pLB;
    cudaGetSymbolAddress((void**)&pu,  g_u);
    cudaGetSymbolAddress((void**)&pv,  g_v);
    cudaGetSymbolAddress((void**)&pSA, g_SA);
    cudaGetSymbolAddress((void**)&pSB, g_SB);
    cudaGetSymbolAddress((void**)&pAA, g_AA);
    cudaGetSymbolAddress((void**)&pAB, g_AB);
    cudaGetSymbolAddress((void**)&pLA, g_LA);
    cudaGetSymbolAddress((void**)&pLB, g_LB);

    cudaFuncSetAttribute(iter2_kernel, cudaFuncAttributeMaxDynamicSharedMemorySize,
                         ITER_DYN_SMEM);

    const int Mrows = BB * LL;  // 4096

    // u and v projections in one launch
    gemm32_kernel<<<dim3(DD/64, (2*Mrows)/128), 256>>>(
        target, Wt, bt, pu, 2*Mrows, DD, DD, 0, 1, context, Wc, bc, pv, Mrows);

    prep_wl2_kernel<<<(NLAM + 255) / 256, 256>>>(Wl2);

    // separable 16-dim projections (fp32 exact + SB fp16 shadow)
    proj_kernel<<<(2*Mrows)/32, 128>>>(target, context, Ws1, Wa1, Wl1,
                                       pSA, pAA, pLA, pSB, pAB, pLB);

    // scores + top-8 (half2 approx prune, exact rescue)
    score_topk_kernel<<<BB * LL, 256>>>(bs1, Ws2, bs2);

    // fused: edge params + in-block Lam generation + both consensus iterations
    iter2_kernel<<<BB * LL, 256, ITER_DYN_SMEM>>>(step_sizes, bl1, ba1, Wa2, ba2, bl2);

    gemm32_kernel<<<dim3(DD/64, Mrows/128), 256>>>(
        pu, Wo, bo, (float*)d_out, Mrows, DD, DD, 1, 0,
        nullptr, nullptr, nullptr, nullptr, 0);
}

// round 7
// speedup vs baseline: 2.3381x; 1.0968x over previous
#include <cuda_runtime.h>
#include <cuda_fp16.h>
#include <cstdint>

// Problem constants
#define BB 2
#define LL 2048
#define KK 2048
#define DD 512
#define HH 8
#define HD 64
#define RR 8
#define WWIN 8
#define EE (LL*WWIN)          // 16384 edges per batch
#define EH 16
#define TT 2
#define NLAM (HH*RR*HD)       // 4096
#define SCAP 256              // survivor cap in score kernel
#define LAMP 4112             // padded halves per edge chunk in iter2 smem (4096+16)

// ---------------- scratch (allocation-free: static device globals) ----------------
__device__ float  g_u [BB*HH*LL*HD];          // [B,H,L,HD]
__device__ float  g_v [BB*HH*KK*HD];          // [B,H,K,HD]
__device__ float  g_SA[BB*LL*EH];
__device__ float  g_SB[BB*KK*EH];
__device__ __half g_SBh[BB*KK*EH];            // fp16 copy for approx scoring
__device__ float  g_AA[BB*LL*EH];
__device__ float  g_AB[BB*KK*EH];
__device__ float  g_LA[BB*LL*EH];
__device__ float  g_LB[BB*KK*EH];
__device__ int    g_idx[BB*LL*WWIN];
__device__ __half g_Wl2h[NLAM*EH];            // Wl2 transposed [n][k] fp16

// ---------------- helpers ----------------
__device__ __forceinline__ float geluf(float x){
    return 0.5f * x * (1.0f + erff(x * 0.7071067811865475244f));
}
__device__ __forceinline__ float softplusf(float x){
    return (x > 20.f) ? x : log1pf(expf(x));
}
__device__ __forceinline__ float tf32_rna(float x){
    uint32_t u;
    asm("cvt.rna.tf32.f32 %0, %1;" : "=r"(u) : "f"(x));
    return __uint_as_float(u);
}
__device__ __forceinline__ unsigned flipf(float s){
    unsigned u = __float_as_uint(s);
    return (u & 0x80000000u) ? ~u : (u | 0x80000000u);
}
__device__ __forceinline__ __half2 tanh2(__half2 x){
    uint32_t r, a = *(uint32_t*)&x;
    asm("tanh.approx.f16x2 %0, %1;" : "=r"(r) : "r"(a));
    return *(__half2*)&r;
}
__device__ __forceinline__ void mma_tf32(float* d, const uint32_t* a, const uint32_t* b){
    asm("mma.sync.aligned.m16n8k8.row.col.f32.tf32.tf32.f32 "
        "{%0,%1,%2,%3}, {%4,%5,%6,%7}, {%8,%9}, {%0,%1,%2,%3};"
        : "+f"(d[0]), "+f"(d[1]), "+f"(d[2]), "+f"(d[3])
        : "r"(a[0]), "r"(a[1]), "r"(a[2]), "r"(a[3]), "r"(b[0]), "r"(b[1]));
}
__device__ __forceinline__ void mma_f16(float* d, uint32_t a0, uint32_t a1, uint32_t a2,
                                        uint32_t a3, uint32_t b0, uint32_t b1){
    asm("mma.sync.aligned.m16n8k16.row.col.f32.f16.f16.f32 "
        "{%0,%1,%2,%3}, {%4,%5,%6,%7}, {%8,%9}, {%0,%1,%2,%3};"
        : "+f"(d[0]), "+f"(d[1]), "+f"(d[2]), "+f"(d[3])
        : "r"(a0), "r"(a1), "r"(a2), "r"(a3), "r"(b0), "r"(b1));
}
__device__ __forceinline__ unsigned long long warp_max_ull(unsigned long long v){
#pragma unroll
    for (int o = 16; o; o >>= 1) {
        unsigned long long w = __shfl_xor_sync(0xffffffffu, v, o);
        if (w > v) v = w;
    }
    return v;
}
__device__ __forceinline__ float warp_fmax(float v){
#pragma unroll
    for (int o = 16; o; o >>= 1)
        v = fmaxf(v, __shfl_xor_sync(0xffffffffu, v, o));
    return v;
}

// ---------------- tf32 tensor-core GEMM: C = A[MxK] @ W[KxN] + bias ----------------
__global__ __launch_bounds__(256) void gemm32_kernel(
    const float* A, const float* W, const float* bias, float* C,
    int M, int N, int Kd, int aload, int smode,
    const float* A2, const float* W2, const float* bias2, float* C2, int halfM)
{
    __shared__ float As[128][36];
    __shared__ float Bs[32][72];
    int bm = blockIdx.y * 128;
    const int bn = blockIdx.x * 64;
    if (halfM && bm >= halfM) { A = A2; W = W2; bias = bias2; C = C2; bm -= halfM; }
    const int tid  = threadIdx.x;
    const int warp = tid >> 5, lane = tid & 31;
    const int wm = warp & 3, wn = warp >> 2;
    const int q = lane >> 2, c = lane & 3;

    float d[2][4][4];
#pragma unroll
    for (int mt = 0; mt < 2; mt++)
#pragma unroll
        for (int nt = 0; nt < 4; nt++)
#pragma unroll
            for (int i = 0; i < 4; i++) d[mt][nt][i] = 0.f;

    for (int k0 = 0; k0 < Kd; k0 += 32) {
#pragma unroll
        for (int i = 0; i < 4; i++) {
            int id = tid + i * 256;
            int m = id >> 3, kq = (id & 7) * 4;
            float4 v;
            if (aload) {
                int mm = bm + m; int b = mm >> 11, l = mm & 2047;
                int k = k0 + kq; int h = k >> 6, hd = k & 63;
                v = *(const float4*)&A[(((size_t)b * HH + h) * LL + l) * HD + hd];
            } else {
                v = *(const float4*)&A[(size_t)(bm + m) * Kd + k0 + kq];
            }
            float4 t = make_float4(tf32_rna(v.x), tf32_rna(v.y), tf32_rna(v.z), tf32_rna(v.w));
            *(float4*)&As[m][kq] = t;
        }
#pragma unroll
        for (int i = 0; i < 2; i++) {
            int id = tid + i * 256;
            int kk = id >> 4, nq = (id & 15) * 4;
            float4 v = *(const float4*)&W[(size_t)(k0 + kk) * N + bn + nq];
            float4 t = make_float4(tf32_rna(v.x), tf32_rna(v.y), tf32_rna(v.z), tf32_rna(v.w));
            *(float4*)&Bs[kk][nq] = t;
        }
        __syncthreads();
#pragma unroll
        for (int k8 = 0; k8 < 4; k8++) {
            uint32_t a[2][4], b[4][2];
#pragma unroll
            for (int mt = 0; mt < 2; mt++) {
                int r0 = wm * 32 + mt * 16 + q;
                a[mt][0] = __float_as_uint(As[r0    ][k8 * 8 + c]);
                a[mt][1] = __float_as_uint(As[r0 + 8][k8 * 8 + c]);
                a[mt][2] = __float_as_uint(As[r0    ][k8 * 8 + c + 4]);
                a[mt][3] = __float_as_uint(As[r0 + 8][k8 * 8 + c + 4]);
            }
#pragma unroll
            for (int nt = 0; nt < 4; nt++) {
                int cn = wn * 32 + nt * 8 + q;
                b[nt][0] = __float_as_uint(Bs[k8 * 8 + c    ][cn]);
                b[nt][1] = __float_as_uint(Bs[k8 * 8 + c + 4][cn]);
            }
#pragma unroll
            for (int mt = 0; mt < 2; mt++)
#pragma unroll
                for (int nt = 0; nt < 4; nt++)
                    mma_tf32(d[mt][nt], a[mt], b[nt]);
        }
        __syncthreads();
    }

#pragma unroll
    for (int mt = 0; mt < 2; mt++) {
        int gm0 = bm + wm * 32 + mt * 16 + q;
#pragma unroll
        for (int nt = 0; nt < 4; nt++) {
            int gn = bn + wn * 32 + nt * 8 + 2 * c;
            float b0 = __ldg(&bias[gn]), b1 = __ldg(&bias[gn + 1]);
            float v0 = d[mt][nt][0] + b0, v1 = d[mt][nt][1] + b1;
            float v2 = d[mt][nt][2] + b0, v3 = d[mt][nt][3] + b1;
            if (smode == 1) {
                int bb = gm0 >> 11, l = gm0 & 2047, h = gn >> 6, hd = gn & 63;
                float* p0 = &C[(((size_t)bb * HH + h) * LL + l) * HD + hd];
                p0[0] = v0; p0[1] = v1;
                float* p2 = &C[(((size_t)bb * HH + h) * LL + (l + 8)) * HD + hd];
                p2[0] = v2; p2[1] = v3;
            } else {
                *(float2*)&C[(size_t)gm0 * N + gn] = make_float2(v0, v1);
                *(float2*)&C[(size_t)(gm0 + 8) * N + gn] = make_float2(v2, v3);
            }
        }
    }
}

// ---------------- Wl2 transpose+convert: [16][4096] f32 -> [4096][16] f16 ----------
__global__ void prep_wl2_kernel(const float* __restrict__ Wl2)
{
    int n = blockIdx.x * blockDim.x + threadIdx.x;
    if (n >= NLAM) return;
#pragma unroll
    for (int k = 0; k < EH; k++)
        g_Wl2h[n * EH + k] = __float2half(Wl2[(size_t)k * NLAM + n]);
}

// ---------------- 512->48 projection (both inputs), 12 cols/thread ----------------
__global__ __launch_bounds__(128) void proj_kernel(
    const float* __restrict__ Xt, const float* __restrict__ Xc,
    const float* __restrict__ W1, const float* __restrict__ W2, const float* __restrict__ W3,
    float* __restrict__ O1t, float* __restrict__ O2t, float* __restrict__ O3t,
    float* __restrict__ O1c, float* __restrict__ O2c, float* __restrict__ O3c)
{
    __shared__ float Xs[32][68];
    __shared__ float Ws[64][52];
    const int grow0 = blockIdx.x * 32;
    const int sel = grow0 >= (BB * LL);
    const float* X = sel ? Xc : Xt;
    const int row0 = grow0 & (BB * LL - 1);
    const int koff = sel ? DD : 0;
    const int tid = threadIdx.x;
    const int r = tid >> 2, c0 = (tid & 3) * 12;

    float acc[12];
#pragma unroll
    for (int j = 0; j < 12; j++) acc[j] = 0.f;

    for (int k0 = 0; k0 < DD; k0 += 64) {
#pragma unroll
        for (int i = 0; i < 4; i++) {
            int id = tid + i * 128;
            int rr = id >> 4, qq = (id & 15) * 4;
            *(float4*)&Xs[rr][qq] = *(const float4*)&X[(size_t)(row0 + rr) * DD + k0 + qq];
        }
#pragma unroll
        for (int i = 0; i < 2; i++) {
            int id = tid + i * 128;
            int kr = id >> 2, qq = (id & 3) * 4;
            *(float4*)&Ws[kr][ 0 + qq] = *(const float4*)&W1[(size_t)(koff + k0 + kr) * EH + qq];
            *(float4*)&Ws[kr][16 + qq] = *(const float4*)&W2[(size_t)(koff + k0 + kr) * EH + qq];
            *(float4*)&Ws[kr][32 + qq] = *(const float4*)&W3[(size_t)(koff + k0 + kr) * EH + qq];
        }
        __syncthreads();
#pragma unroll
        for (int k = 0; k < 64; k++) {
            float x = Xs[r][k];
            float4 w0 = *(const float4*)&Ws[k][c0];
            float4 w1 = *(const float4*)&Ws[k][c0 + 4];
            float4 w2 = *(const float4*)&Ws[k][c0 + 8];
            acc[0] += x * w0.x;  acc[1] += x * w0.y;  acc[2]  += x * w0.z;  acc[3]  += x * w0.w;
            acc[4] += x * w1.x;  acc[5] += x * w1.y;  acc[6]  += x * w1.z;  acc[7]  += x * w1.w;
            acc[8] += x * w2.x;  acc[9] += x * w2.y;  acc[10] += x * w2.z;  acc[11] += x * w2.w;
        }
        __syncthreads();
    }

    const int row = row0 + r;
#pragma unroll
    for (int j = 0; j < 12; j++) {
        int cc = c0 + j;
        int m = cc >> 4, col = cc & 15;
        float* O = sel ? (m == 0 ? O1c : m == 1 ? O2c : O3c)
                       : (m == 0 ? O1t : m == 1 ? O2t : O3t);
        O[(size_t)row * EH + col] = acc[j];
        if (sel && m == 0)
            g_SBh[(size_t)row * EH + col] = __float2half(acc[j]);
    }
}

// ---------------- score + top-8: half2 approx, float-only threshold, exact rescue --
// Threshold via order statistics: the 8th-largest of the 256 per-thread maxima is
// <= the global approx 8th-largest (the top-8 thread-maxes are 8 distinct actual
// scores), so thr = t8' - margin only ADMITS MORE survivors — provably safe.
// Duplicate-value self-zeroing in the fmax passes also only lowers t8' — safe.
__global__ __launch_bounds__(256) void score_topk_kernel(
    const float* __restrict__ bs1, const float* __restrict__ Ws2, const float* __restrict__ bs2)
{
    __shared__ float a16[EH];
    __shared__ float w2s[EH];
    __shared__ __half2 a2h[8];
    __shared__ __half2 w2h[8];
    __shared__ float s_wv[8][8];
    __shared__ unsigned long long s_wk[8][8];
    __shared__ int s_surv[SCAP];
    __shared__ int s_cnt;
    __shared__ float s_thr;

    int b = blockIdx.x >> 11, l = blockIdx.x & 2047;
    int tid = threadIdx.x;
    int warp = tid >> 5, lane = tid & 31;
    if (tid < EH) {
        a16[tid] = g_SA[((size_t)b * LL + l) * EH + tid] + bs1[tid];
        w2s[tid] = Ws2[tid];
    }
    __syncthreads();
    if (tid < 8) {
        a2h[tid] = __floats2half2_rn(a16[2 * tid], a16[2 * tid + 1]);
        w2h[tid] = __floats2half2_rn(w2s[2 * tid], w2s[2 * tid + 1]);
    }
    __syncthreads();
    float aR[EH], wR[EH];
#pragma unroll
    for (int c = 0; c < EH; c++) { aR[c] = a16[c]; wR[c] = w2s[c]; }
    __half2 aH[8], wH[8];
#pragma unroll
    for (int c = 0; c < 8; c++) { aH[c] = a2h[c]; wH[c] = w2h[c]; }
    float bs2v = bs2[0];
    const __half2 C1 = __float2half2_rn(0.0356774081f);   // 0.79788456*0.044715
    const __half2 C0 = __float2half2_rn(0.7978845608f);
    const __half2 H5 = __float2half2_rn(0.5f);
    const float NINF = __int_as_float(0xff800000);

    // phase A: half2 approx scores -> registers, track per-thread max (no keys)
    float s8[8];
    float tmax = NINF;
#pragma unroll
    for (int i = 0; i < 8; i++) {
        int kk = tid + i * 256;
        const uint4* bp = (const uint4*)(g_SBh + ((size_t)b * KK + kk) * EH);
        uint4 r0 = bp[0], r1 = bp[1];
        uint32_t bw[8] = {r0.x, r0.y, r0.z, r0.w, r1.x, r1.y, r1.z, r1.w};
        __half2 acc = __float2half2_rn(0.f);
#pragma unroll
        for (int c = 0; c < 8; c++) {
            __half2 h  = __hadd2(aH[c], *(__half2*)&bw[c]);
            __half2 p  = __hmul2(h, h);
            __half2 qq = __hfma2(p, C1, C0);
            __half2 t  = __hmul2(h, qq);
            __half2 th = tanh2(t);
            __half2 hh = __hmul2(h, H5);
            __half2 rs = __hfma2(hh, th, hh);
            acc = __hfma2(rs, wH[c], acc);
        }
        float2 f = __half22float2(acc);
        float s = f.x + f.y + bs2v;
        s8[i] = s;
        tmax = fmaxf(tmax, s);
    }

    // warp top-8 over 32 thread-maxes (pure fp32 fmax + shuffle)
    {
        float v = tmax;
#pragma unroll
        for (int p = 0; p < 8; p++) {
            float best = warp_fmax(v);
            if (v == best) v = NINF;      // dup-zeroing only lowers t8' -> safe
            if (lane == 0) s_wv[warp][p] = best;
        }
    }
    __syncthreads();

    // warp 0: merge 64 -> t8' and threshold
    if (warp == 0) {
        float va = ((float*)s_wv)[lane];
        float vb = ((float*)s_wv)[lane + 32];
        float t8 = NINF;
#pragma unroll
        for (int p = 0; p < 8; p++) {
            float m = fmaxf(va, vb);
            float best = warp_fmax(m);
            if (va == best) va = NINF; else if (vb == best) vb = NINF;
            t8 = best;
        }
        if (lane == 0) {
            float sw = 0.f;
#pragma unroll
            for (int c = 0; c < EH; c++) sw += fabsf(w2s[c]);
            s_thr = t8 - (sw * 0.03f + 0.06f);
            s_cnt = 0;
        }
    }
    __syncthreads();

    // survivor scan from register scores
    float thr = s_thr;
#pragma unroll
    for (int i = 0; i < 8; i++) {
        if (s8[i] >= thr) {
            int p = atomicAdd(&s_cnt, 1);
            if (p < SCAP) s_surv[p] = tid + i * 256;
        }
    }
    __syncthreads();
    int n = s_cnt;
    bool fb = (n > SCAP);

    unsigned long long key = 0ull;
    if (!fb) {
        if (tid < n) {
            int kk = s_surv[tid];
            const float4* bp = (const float4*)(g_SB + ((size_t)b * KK + kk) * EH);
            float4 b0 = bp[0], b1 = bp[1], b2 = bp[2], b3 = bp[3];
            float bv[EH] = {b0.x,b0.y,b0.z,b0.w, b1.x,b1.y,b1.z,b1.w,
                            b2.x,b2.y,b2.z,b2.w, b3.x,b3.y,b3.z,b3.w};
            float s = bs2v;
#pragma unroll
            for (int c = 0; c < EH; c++) s += geluf(aR[c] + bv[c]) * wR[c];
            key = (((unsigned long long)flipf(s)) << 32) | (unsigned)(KK - 1 - kk);
        }
#pragma unroll
        for (int p = 0; p < 8; p++) {
            unsigned long long best = warp_max_ull(key);
            if (key == best && best != 0ull) key = 0ull;
            if (lane == 0) s_wk[warp][p] = best;
        }
    } else {
        // fallback: exact rescore of everything (rare)
        unsigned long long k8[8];
#pragma unroll
        for (int i = 0; i < 8; i++) {
            int kk = tid + i * 256;
            const float4* bp = (const float4*)(g_SB + ((size_t)b * KK + kk) * EH);
            float4 b0 = bp[0], b1 = bp[1], b2 = bp[2], b3 = bp[3];
            float bv[EH] = {b0.x,b0.y,b0.z,b0.w, b1.x,b1.y,b1.z,b1.w,
                            b2.x,b2.y,b2.z,b2.w, b3.x,b3.y,b3.z,b3.w};
            float s = bs2v;
#pragma unroll
            for (int c = 0; c < EH; c++) s += geluf(aR[c] + bv[c]) * wR[c];
            k8[i] = (((unsigned long long)flipf(s)) << 32) | (unsigned)(KK - 1 - kk);
        }
        unsigned long long lm = k8[0]; int am = 0;
#pragma unroll
        for (int i = 1; i < 8; i++) if (k8[i] > lm) { lm = k8[i]; am = i; }
#pragma unroll
        for (int p = 0; p < 8; p++) {
            unsigned long long best = warp_max_ull(lm);
            if (lm == best && best != 0ull) {
                k8[am] = 0ull;
                lm = k8[0]; am = 0;
#pragma unroll
                for (int i = 1; i < 8; i++) if (k8[i] > lm) { lm = k8[i]; am = i; }
            }
            if (lane == 0) s_wk[warp][p] = best;
        }
    }
    __syncthreads();

    if (warp == 0) {
        unsigned long long ka = ((unsigned long long*)s_wk)[lane];
        unsigned long long kb = ((unsigned long long*)s_wk)[lane + 32];
#pragma unroll
        for (int p = 0; p < 8; p++) {
            unsigned long long m = ka > kb ? ka : kb;
            unsigned long long best = warp_max_ull(m);
            if (ka == best) ka = 0ull; else if (kb == best) kb = 0ull;
            if (lane == 0)
                g_idx[((size_t)b * LL + l) * WWIN + p] = KK - 1 - (int)(best & 0xffffffffu);
        }
    }
}

// ---------------- fused consensus: gh/alpha + in-block Lam MMA + T=2 iterations ---
#define ITER_DYN_SMEM (8*LAMP*2 + 8*HH*HD*4)   // 65792 + 16384 = 82176 B
__global__ __launch_bounds__(256) void iter2_kernel(
    const float* __restrict__ step_sizes, const float* __restrict__ bl1,
    const float* __restrict__ ba1, const float* __restrict__ Wa2,
    const float* __restrict__ ba2, const float* __restrict__ bl2)
{
    extern __shared__ char dyn[];
    __half* s_lam = (__half*)dyn;                        // [8e] x LAMP halves
    float*  s_v   = (float*)(dyn + 8*LAMP*2);            // [8e][H][64]
    __shared__ float s_cs[8][32];
    __shared__ float s_sn[8][32];
    __shared__ float s_alpha[8];
    __shared__ int   s_idx[8];
    __shared__ __half s_gh[8][EH];

    int b = blockIdx.x >> 11, l = blockIdx.x & 2047;
    int tid = threadIdx.x;
    int wi = tid >> 5, ln = tid & 31;
    int eg = ln >> 3, dg = ln & 7;
    int q = ln >> 2, cq = ln & 3;

    // per-edge small params: warp e owns edge e
    {
        int e = wi;
        int j = g_idx[((size_t)b * LL + l) * WWIN + e];
        if (ln == 0) s_idx[e] = j;
        float hav = 0.f;
        if (ln < EH) {
            int c = ln;
            float hl = g_LA[((size_t)b * LL + l) * EH + c]
                     + g_LB[((size_t)b * KK + j) * EH + c] + bl1[c];
            s_gh[e][c] = __float2half(geluf(hl));
            float ha = g_AA[((size_t)b * LL + l) * EH + c]
                     + g_AB[((size_t)b * KK + j) * EH + c] + ba1[c];
            hav = geluf(ha) * Wa2[c];
        }
#pragma unroll
        for (int o = 16; o; o >>= 1) hav += __shfl_xor_sync(0xffffffffu, hav, o);
        if (ln == 0) s_alpha[e] = softplusf(hav + ba2[0]);
        float ang = (float)(l - j) * exp2f((float)ln * -0.41524101186092029f);
        s_cs[e][ln] = cosf(ang);
        s_sn[e][ln] = sinf(ang);
    }
    __syncthreads();

    // stage gathered v rows
#pragma unroll
    for (int i = 0; i < 16; i++) {
        int gid = tid + i * 256;
        int e2 = gid >> 9, h2 = (gid >> 6) & 7, d = gid & 63;
        s_v[gid] = g_v[(((size_t)b * HH + h2) * KK + s_idx[e2]) * HD + d];
    }

    // generate Lam for head wi: rows = edges (A rows 0-7 valid), 512 cols per warp
    {
        uint32_t A0 = *(const uint32_t*)&s_gh[q][2 * cq];
        uint32_t A2 = *(const uint32_t*)&s_gh[q][2 * cq + 8];
        uint32_t Z = 0u;
#pragma unroll
        for (int rr = 0; rr < 8; rr++) {
            float v0a[8], v1a[8];
            float ssq = 0.f;
#pragma unroll
            for (int ii = 0; ii < 8; ii++) {
                int colq = wi * 512 + (rr * 8 + ii) * 8 + q;       // B col this thread
                const uint32_t* bp = (const uint32_t*)(g_Wl2h + (size_t)colq * EH);
                uint32_t b0 = bp[cq], b1 = bp[cq + 4];
                float dd[4] = {0.f, 0.f, 0.f, 0.f};
                mma_f16(dd, A0, Z, A2, Z, b0, b1);
                int ncol = wi * 512 + (rr * 8 + ii) * 8 + 2 * cq;  // output cols (edge q)
                float2 bb = *(const float2*)&bl2[ncol];
                v0a[ii] = dd[0] + bb.x;
                v1a[ii] = dd[1] + bb.y;
                ssq += v0a[ii] * v0a[ii] + v1a[ii] * v1a[ii];
            }
            ssq += __shfl_xor_sync(0xffffffffu, ssq, 1);
            ssq += __shfl_xor_sync(0xffffffffu, ssq, 2);
            float sc = 1.f / fmaxf(sqrtf(ssq), 1e-12f);
#pragma unroll
            for (int ii = 0; ii < 8; ii++) {
                int ncol = wi * 512 + (rr * 8 + ii) * 8 + 2 * cq;
                *(__half2*)&s_lam[(size_t)q * LAMP + ncol] =
                    __floats2half2_rn(v0a[ii] * sc, v1a[ii] * sc);
            }
        }
    }
    __syncthreads();

    size_t ubase = (((size_t)b * HH + wi) * LL + l) * HD;
    float4 u_lo = *(const float4*)&g_u[ubase + dg * 4];
    float4 u_hi = *(const float4*)&g_u[ubase + 32 + dg * 4];

#pragma unroll
    for (int t = 0; t < TT; t++) {
        float stp = softplusf(step_sizes[t * LL + l]);
        float al4[4] = {0.f,0.f,0.f,0.f}, ah4[4] = {0.f,0.f,0.f,0.f};
#pragma unroll
        for (int eb = 0; eb < 2; eb++) {
            int e = eb * 4 + eg;
            float4 cs4 = *(const float4*)&s_cs[e][dg * 4];
            float4 sn4 = *(const float4*)&s_sn[e][dg * 4];
            const float4* vp = (const float4*)&s_v[(e * HH + wi) * HD + dg * 4];
            float4 vlo = vp[0], vhi = vp[8];
            float dlo[4], dhi[4];
            dlo[0] = u_lo.x * cs4.x - u_hi.x * sn4.x - vlo.x;
            dlo[1] = u_lo.y * cs4.y - u_hi.y * sn4.y - vlo.y;
            dlo[2] = u_lo.z * cs4.z - u_hi.z * sn4.z - vlo.z;
            dlo[3] = u_lo.w * cs4.w - u_hi.w * sn4.w - vlo.w;
            dhi[0] = u_hi.x * cs4.x + u_lo.x * sn4.x - vhi.x;
            dhi[1] = u_hi.y * cs4.y + u_lo.y * sn4.y - vhi.y;
            dhi[2] = u_hi.z * cs4.z + u_lo.z * sn4.z - vhi.z;
            dhi[3] = u_hi.w * cs4.w + u_lo.w * sn4.w - vhi.w;
            float alp = s_alpha[e];
            float rl[4] = {0.f,0.f,0.f,0.f}, rh[4] = {0.f,0.f,0.f,0.f};
            const __half2* lp = (const __half2*)(s_lam + (size_t)e * LAMP + wi * RR * HD);
#pragma unroll
            for (int r = 0; r < RR; r++) {
                __half2 hl0 = lp[r * 32 + dg * 2], hl1 = lp[r * 32 + dg * 2 + 1];
                __half2 hh0 = lp[r * 32 + 16 + dg * 2], hh1 = lp[r * 32 + 16 + dg * 2 + 1];
                float2 f0 = __half22float2(hl0), f1 = __half22float2(hl1);
                float2 f2 = __half22float2(hh0), f3 = __half22float2(hh1);
                float p = f0.x * dlo[0] + f0.y * dlo[1] + f1.x * dlo[2] + f1.y * dlo[3]
                        + f2.x * dhi[0] + f2.y * dhi[1] + f3.x * dhi[2] + f3.y * dhi[3];
                p += __shfl_xor_sync(0xffffffffu, p, 1);
                p += __shfl_xor_sync(0xffffffffu, p, 2);
                p += __shfl_xor_sync(0xffffffffu, p, 4);
                rl[0] += p * f0.x; rl[1] += p * f0.y; rl[2] += p * f1.x; rl[3] += p * f1.y;
                rh[0] += p * f2.x; rh[1] += p * f2.y; rh[2] += p * f3.x; rh[3] += p * f3.y;
            }
#pragma unroll
            for (int i = 0; i < 4; i++) {
                al4[i] += alp * dlo[i] + rl[i];
                ah4[i] += alp * dhi[i] + rh[i];
            }
        }
#pragma unroll
        for (int i = 0; i < 4; i++) {
            al4[i] += __shfl_xor_sync(0xffffffffu, al4[i], 8);
            al4[i] += __shfl_xor_sync(0xffffffffu, al4[i], 16);
            ah4[i] += __shfl_xor_sync(0xffffffffu, ah4[i], 8);
            ah4[i] += __shfl_xor_sync(0xffffffffu, ah4[i], 16);
        }
        u_lo.x -= stp * al4[0]; u_lo.y -= stp * al4[1];
        u_lo.z -= stp * al4[2]; u_lo.w -= stp * al4[3];
        u_hi.x -= stp * ah4[0]; u_hi.y -= stp * ah4[1];
        u_hi.z -= stp * ah4[2]; u_hi.w -= stp * ah4[3];
    }
    if (eg == 0) {
        *(float4*)&g_u[ubase + dg * 4] = u_lo;
        *(float4*)&g_u[ubase + 32 + dg * 4] = u_hi;
    }
}

// ---------------- launch ----------------
extern "C" void kernel_launch(void* const* d_in, const int* in_sizes, int n_in,
                              void* d_out, int out_size)
{
    const float* target = (const float*)d_in[0];
    const float* context= (const float*)d_in[1];
    const float* Wt  = (const float*)d_in[2];
    const float* bt  = (const float*)d_in[3];
    const float* Wc  = (const float*)d_in[4];
    const float* bc  = (const float*)d_in[5];
    const float* Ws1 = (const float*)d_in[6];
    const float* bs1 = (const float*)d_in[7];
    const float* Ws2 = (const float*)d_in[8];
    const float* bs2 = (const float*)d_in[9];
    const float* Wa1 = (const float*)d_in[10];
    const float* ba1 = (const float*)d_in[11];
    const float* Wa2 = (const float*)d_in[12];
    const float* ba2 = (const float*)d_in[13];
    const float* Wl1 = (const float*)d_in[14];
    const float* bl1 = (const float*)d_in[15];
    const float* Wl2 = (const float*)d_in[16];
    const float* bl2 = (const float*)d_in[17];
    const float* step_sizes = (const float*)d_in[18];
    const float* Wo  = (const float*)d_in[19];
    const float* bo  = (const float*)d_in[20];

    float *pu, *pv, *pSA, *pSB, *pAA, *pAB, *pLA, *pLB;
    cudaGetSymbolAddress((void**)&pu,  g_u);
    cudaGetSymbolAddress((void**)&pv,  g_v);
    cudaGetSymbolAddress((void**)&pSA, g_SA);
    cudaGetSymbolAddress((void**)&pSB, g_SB);
    cudaGetSymbolAddress((void**)&pAA, g_AA);
    cudaGetSymbolAddress((void**)&pAB, g_AB);
    cudaGetSymbolAddress((void**)&pLA, g_LA);
    cudaGetSymbolAddress((void**)&pLB, g_LB);

    cudaFuncSetAttribute(iter2_kernel, cudaFuncAttributeMaxDynamicSharedMemorySize,
                         ITER_DYN_SMEM);

    const int Mrows = BB * LL;  // 4096

    // u and v projections in one launch
    gemm32_kernel<<<dim3(DD/64, (2*Mrows)/128), 256>>>(
        target, Wt, bt, pu, 2*Mrows, DD, DD, 0, 1, context, Wc, bc, pv, Mrows);

    prep_wl2_kernel<<<(NLAM + 255) / 256, 256>>>(Wl2);

    // separable 16-dim projections (fp32 exact + SB fp16 shadow)
    proj_kernel<<<(2*Mrows)/32, 128>>>(target, context, Ws1, Wa1, Wl1,
                                       pSA, pAA, pLA, pSB, pAB, pLB);

    // scores + top-8 (half2 approx, float threshold, exact rescue)
    score_topk_kernel<<<BB * LL, 256>>>(bs1, Ws2, bs2);

    // fused: edge params + in-block Lam generation + both consensus iterations
    iter2_kernel<<<BB * LL, 256, ITER_DYN_SMEM>>>(step_sizes, bl1, ba1, Wa2, ba2, bl2);

    gemm32_kernel<<<dim3(DD/64, Mrows/128), 256>>>(
        pu, Wo, bo, (float*)d_out, Mrows, DD, DD, 1, 0,
        nullptr, nullptr, nullptr, nullptr, 0);
}